// round 9
// baseline (speedup 1.0000x reference)
#include <cuda_runtime.h>
#include <math.h>
#include <stdint.h>

// ---------------- problem constants -----------------------------------------
#define NNODE 19200
#define NEDGE 230400
#define NGRAPH 128
#define LATENT 256
#define FEAT 64
#define HEADS 4
#define POS 180
#define DMODEL 256       // HEADS * FEAT
#define ETOT (NEDGE + NNODE)
#define NBLK 75          // NNODE / 256
#define EBLK 900         // NEDGE / 256
#define WBLK 2400        // NNODE / 8 (8 warps per block)

// ---------------- static device scratch --------------------------------------
__device__ __align__(16) float g_bufA[NNODE * DMODEL];
__device__ __align__(16) float g_bufB[NNODE * DMODEL];
__device__ __align__(16) float g_as[NNODE * HEADS];
__device__ __align__(16) float g_ad[NNODE * HEADS];
__device__ __align__(16) float g_ex[ETOT * HEADS];
__device__ __align__(16) float g_pg[NGRAPH * DMODEL];
__device__ int g_starts[NGRAPH];
__device__ int g_deg[NNODE];      // zero at load; re-zeroed each replay in k_mid
__device__ int g_rowptr[NNODE + 1];
__device__ int g_cursor[NNODE];
__device__ int g_csrc[ETOT];

// ---------------- fused prologue: x0pg | starts | hist -------------------------
__global__ void k_pro(const float* __restrict__ z, const float* __restrict__ W0,
                      const float* __restrict__ b0, const float* __restrict__ W1,
                      float* __restrict__ pg, const int* __restrict__ batch,
                      int* __restrict__ starts, int* __restrict__ deg,
                      const int* __restrict__ dst) {
    int b = blockIdx.x;
    int t = threadIdx.x;
    if (b < NGRAPH) {
        __shared__ float xs[FEAT];
        if (t < FEAT) {
            float acc = b0[t];
            const float* zr = z + b * LATENT;
            #pragma unroll 4
            for (int k = 0; k < LATENT; k++) acc += zr[k] * W0[k * FEAT + t];
            xs[t] = acc > 0.0f ? acc : 0.0f;
        }
        __syncthreads();
        float a = 0.0f;
        #pragma unroll
        for (int k = 0; k < FEAT; k++) a += xs[k] * W1[k * DMODEL + t];
        pg[b * DMODEL + t] = a;
    } else if (b < NGRAPH + NBLK) {
        int i = (b - NGRAPH) * 256 + t;
        int bb = batch[i];
        if (i == 0 || batch[i - 1] != bb) starts[bb] = i;
    } else {
        int e = (b - NGRAPH - NBLK) * 256 + t;
        atomicAdd(&deg[dst[e]], 1);
    }
}

// ---------------- CSR: prefix + local scan + self-loop fill --------------------
__global__ void k_fill2(const int* __restrict__ deg, int* __restrict__ rowptr,
                        int* __restrict__ cursor, int* __restrict__ csrc) {
    __shared__ int red[256];
    __shared__ int s[256];
    int t = threadIdx.x;
    int b = blockIdx.x;
    int lim = b * 256;
    int sum = 0;
    for (int i = t; i < lim; i += 256) sum += deg[i] + 1;   // +1 self loop
    red[t] = sum;
    __syncthreads();
    for (int off = 128; off > 0; off >>= 1) {
        if (t < off) red[t] += red[t + off];
        __syncthreads();
    }
    int node = lim + t;
    int d = deg[node] + 1;
    s[t] = d;
    __syncthreads();
    for (int off = 1; off < 256; off <<= 1) {
        int u = (t >= off) ? s[t - off] : 0;
        __syncthreads();
        s[t] += u;
        __syncthreads();
    }
    int r = red[0] + s[t] - d;
    rowptr[node] = r;
    csrc[r] = node;                           // self loop first
    cursor[node] = r + 1;
    if (node == NNODE - 1) rowptr[NNODE] = red[0] + s[t];
}

// ---------------- fused: h1+attn | CSR scatter | deg re-zero --------------------
__global__ void k_mid(const float* __restrict__ pg, const float* __restrict__ W1,
                      const int* __restrict__ batch, const int* __restrict__ starts,
                      const float* __restrict__ attS, const float* __restrict__ attD,
                      float* __restrict__ H, float* __restrict__ aS,
                      float* __restrict__ aD,
                      const int* __restrict__ src, const int* __restrict__ dst,
                      int* __restrict__ cursor, int* __restrict__ csrc,
                      int* __restrict__ deg) {
    int b = blockIdx.x;
    int tid = threadIdx.x;
    if (b >= WBLK + EBLK) {
        deg[(b - WBLK - EBLK) * 256 + tid] = 0;
        return;
    }
    if (b >= WBLK) {
        int e = (b - WBLK) * 256 + tid;
        int p = atomicAdd(&cursor[dst[e]], 1);
        csrc[p] = src[e];
        return;
    }
    __shared__ float sS[DMODEL], sD[DMODEL];
    if (tid < DMODEL) { sS[tid] = attS[tid]; sD[tid] = attD[tid]; }
    __syncthreads();
    int node = b * 8 + (tid >> 5);
    int lane = tid & 31;
    int g = batch[node];
    int order = node - starts[g];
    int c0 = lane * 8;
    const float4* pgr = (const float4*)(pg + g * DMODEL + c0);
    const float4* w1r = (const float4*)(W1 + (FEAT + order) * DMODEL + c0);
    float4 p0 = pgr[0], p1 = pgr[1];
    float4 w0 = w1r[0], w1v = w1r[1];
    float h[8];
    h[0] = p0.x + w0.x; h[1] = p0.y + w0.y; h[2] = p0.z + w0.z; h[3] = p0.w + w0.w;
    h[4] = p1.x + w1v.x; h[5] = p1.y + w1v.y; h[6] = p1.z + w1v.z; h[7] = p1.w + w1v.w;
    float* hr = H + node * DMODEL + c0;
    *(float4*)hr       = make_float4(h[0], h[1], h[2], h[3]);
    *(float4*)(hr + 4) = make_float4(h[4], h[5], h[6], h[7]);
    float pS = 0.0f, pD = 0.0f;
    #pragma unroll
    for (int j = 0; j < 8; j++) { pS += h[j] * sS[c0 + j]; pD += h[j] * sD[c0 + j]; }
    pS += __shfl_xor_sync(0xffffffffu, pS, 1);
    pS += __shfl_xor_sync(0xffffffffu, pS, 2);
    pS += __shfl_xor_sync(0xffffffffu, pS, 4);
    pD += __shfl_xor_sync(0xffffffffu, pD, 1);
    pD += __shfl_xor_sync(0xffffffffu, pD, 2);
    pD += __shfl_xor_sync(0xffffffffu, pD, 4);
    if ((lane & 7) == 0) {
        int hd = lane >> 3;
        aS[node * 4 + hd] = pS;
        aD[node * 4 + hd] = pD;
    }
}

// ---------------- tf32 tensor-core GEMM + fused attention logits ---------------
#define SMS 136
__device__ __forceinline__ uint32_t f2tf32(float v) {
    uint32_t r;
    asm("cvt.rna.tf32.f32 %0, %1;" : "=r"(r) : "f"(v));
    return r;
}
__device__ __forceinline__ void mma_tf32(float* c, uint32_t a0, uint32_t a1,
                                         uint32_t a2, uint32_t a3,
                                         uint32_t b0, uint32_t b1) {
    asm volatile(
        "mma.sync.aligned.m16n8k8.row.col.f32.tf32.tf32.f32 "
        "{%0,%1,%2,%3}, {%4,%5,%6,%7}, {%8,%9}, {%0,%1,%2,%3};"
        : "+f"(c[0]), "+f"(c[1]), "+f"(c[2]), "+f"(c[3])
        : "r"(a0), "r"(a1), "r"(a2), "r"(a3), "r"(b0), "r"(b1));
}

__global__ void __launch_bounds__(256, 1)
k_gemm_attn(const float* __restrict__ X, const float* __restrict__ W,
            const float* __restrict__ attS, const float* __restrict__ attD,
            float* __restrict__ C, float* __restrict__ aS, float* __restrict__ aD) {
    __shared__ uint32_t As[32][SMS];
    __shared__ uint32_t Bs[32][SMS];
    __shared__ float sS[128], sD[128];
    __shared__ float sPS[128][2], sPD[128][2];

    int tid = threadIdx.x;
    int lane = tid & 31;
    int w = tid >> 5;
    int wm = w & 1, wn = w >> 1;
    int r0 = blockIdx.x * 128;
    int c0 = blockIdx.y * 128;

    if (tid < 128) { sS[tid] = attS[c0 + tid]; sD[tid] = attD[c0 + tid]; }
    {
        int rr = tid >> 1, hh = tid & 1;
        sPS[rr][hh] = 0.0f;
        sPD[rr][hh] = 0.0f;
    }

    float acc[4][4][4];
    #pragma unroll
    for (int i = 0; i < 4; i++)
        #pragma unroll
        for (int j = 0; j < 4; j++)
            #pragma unroll
            for (int q = 0; q < 4; q++) acc[i][j][q] = 0.0f;

    int am = tid >> 1;
    int ak = (tid & 1) * 16;
    int bkr = tid >> 3;
    int bn = (tid & 7) * 16;

    #pragma unroll 1
    for (int kc = 0; kc < DMODEL; kc += 32) {
        const float4* ap = (const float4*)(X + (r0 + am) * DMODEL + kc + ak);
        #pragma unroll
        for (int q = 0; q < 4; q++) {
            float4 v = ap[q];
            As[ak + q * 4 + 0][am] = f2tf32(v.x);
            As[ak + q * 4 + 1][am] = f2tf32(v.y);
            As[ak + q * 4 + 2][am] = f2tf32(v.z);
            As[ak + q * 4 + 3][am] = f2tf32(v.w);
        }
        const float4* bp = (const float4*)(W + (kc + bkr) * DMODEL + c0 + bn);
        #pragma unroll
        for (int q = 0; q < 4; q++) {
            float4 v = bp[q];
            uint4 u;
            u.x = f2tf32(v.x); u.y = f2tf32(v.y);
            u.z = f2tf32(v.z); u.w = f2tf32(v.w);
            *(uint4*)&Bs[bkr][bn + q * 4] = u;
        }
        __syncthreads();

        #pragma unroll
        for (int kk = 0; kk < 4; kk++) {
            int kb = kk * 8;
            int klo = kb + (lane & 3), khi = klo + 4;
            uint32_t afr[4][4], bfr[4][2];
            #pragma unroll
            for (int mt = 0; mt < 4; mt++) {
                int m = wm * 64 + mt * 16 + (lane >> 2);
                afr[mt][0] = As[klo][m];
                afr[mt][1] = As[klo][m + 8];
                afr[mt][2] = As[khi][m];
                afr[mt][3] = As[khi][m + 8];
            }
            #pragma unroll
            for (int nt = 0; nt < 4; nt++) {
                int n = wn * 32 + nt * 8 + (lane >> 2);
                bfr[nt][0] = Bs[klo][n];
                bfr[nt][1] = Bs[khi][n];
            }
            #pragma unroll
            for (int mt = 0; mt < 4; mt++)
                #pragma unroll
                for (int nt = 0; nt < 4; nt++)
                    mma_tf32(acc[mt][nt], afr[mt][0], afr[mt][1], afr[mt][2],
                             afr[mt][3], bfr[nt][0], bfr[nt][1]);
        }
        __syncthreads();
    }

    int hb = wn >> 1;
    #pragma unroll
    for (int mt = 0; mt < 4; mt++) {
        int rowA = wm * 64 + mt * 16 + (lane >> 2);
        int rowB = rowA + 8;
        float pSa = 0.0f, pDa = 0.0f, pSb = 0.0f, pDb = 0.0f;
        #pragma unroll
        for (int nt = 0; nt < 4; nt++) {
            int lc = wn * 32 + nt * 8 + 2 * (lane & 3);
            float s0 = sS[lc], s1 = sS[lc + 1];
            float d0 = sD[lc], d1 = sD[lc + 1];
            float* a = acc[mt][nt];
            pSa += a[0] * s0 + a[1] * s1;
            pDa += a[0] * d0 + a[1] * d1;
            pSb += a[2] * s0 + a[3] * s1;
            pDb += a[2] * d0 + a[3] * d1;
            float* cpA = C + (r0 + rowA) * DMODEL + c0 + lc;
            float* cpB = C + (r0 + rowB) * DMODEL + c0 + lc;
            *(float2*)cpA = make_float2(a[0], a[1]);
            *(float2*)cpB = make_float2(a[2], a[3]);
        }
        pSa += __shfl_xor_sync(0xffffffffu, pSa, 1);
        pSa += __shfl_xor_sync(0xffffffffu, pSa, 2);
        pDa += __shfl_xor_sync(0xffffffffu, pDa, 1);
        pDa += __shfl_xor_sync(0xffffffffu, pDa, 2);
        pSb += __shfl_xor_sync(0xffffffffu, pSb, 1);
        pSb += __shfl_xor_sync(0xffffffffu, pSb, 2);
        pDb += __shfl_xor_sync(0xffffffffu, pDb, 1);
        pDb += __shfl_xor_sync(0xffffffffu, pDb, 2);
        if ((lane & 3) == 0) {
            atomicAdd(&sPS[rowA][hb], pSa);
            atomicAdd(&sPD[rowA][hb], pDa);
            atomicAdd(&sPS[rowB][hb], pSb);
            atomicAdd(&sPD[rowB][hb], pDb);
        }
    }
    __syncthreads();
    {
        int rr = tid >> 1, hh = tid & 1;
        int node = r0 + rr;
        int head = blockIdx.y * 2 + hh;
        aS[node * 4 + head] = sPS[rr][hh];
        aD[node * 4 + head] = sPD[rr][hh];
    }
}

// ---------------- segment softmax + weighted aggregate (device body) ----------
__device__ __forceinline__ float lrelu(float v) { return v > 0.0f ? v : 0.2f * v; }

__device__ __forceinline__ void aggregate_node(
    int node, int lane, const int* __restrict__ rowptr, const int* __restrict__ csrc,
    const float* __restrict__ H, const float* __restrict__ aS,
    const float* __restrict__ aD, const float* __restrict__ bias,
    float* __restrict__ ex, float r[8]) {
    int rs = rowptr[node], re = rowptr[node + 1];
    float4 ad = *(const float4*)(aD + node * 4);

    // pass 1: logits -> ex (raw), track max
    float m0 = -1e30f, m1 = -1e30f, m2 = -1e30f, m3 = -1e30f;
    for (int e = rs + lane; e < re; e += 32) {
        int s = csrc[e];
        float4 as = *(const float4*)(aS + s * 4);
        float e0 = lrelu(as.x + ad.x);
        float e1 = lrelu(as.y + ad.y);
        float e2 = lrelu(as.z + ad.z);
        float e3 = lrelu(as.w + ad.w);
        *(float4*)(ex + e * 4) = make_float4(e0, e1, e2, e3);
        m0 = fmaxf(m0, e0); m1 = fmaxf(m1, e1);
        m2 = fmaxf(m2, e2); m3 = fmaxf(m3, e3);
    }
    #pragma unroll
    for (int o = 16; o > 0; o >>= 1) {
        m0 = fmaxf(m0, __shfl_xor_sync(0xffffffffu, m0, o));
        m1 = fmaxf(m1, __shfl_xor_sync(0xffffffffu, m1, o));
        m2 = fmaxf(m2, __shfl_xor_sync(0xffffffffu, m2, o));
        m3 = fmaxf(m3, __shfl_xor_sync(0xffffffffu, m3, o));
    }
    // pass 1b: exp over L1-hot ex, write back, sum
    float s0 = 0, s1 = 0, s2 = 0, s3 = 0;
    for (int e = rs + lane; e < re; e += 32) {
        float4 ev = *(const float4*)(ex + e * 4);
        float x0 = expf(ev.x - m0);
        float x1 = expf(ev.y - m1);
        float x2 = expf(ev.z - m2);
        float x3 = expf(ev.w - m3);
        *(float4*)(ex + e * 4) = make_float4(x0, x1, x2, x3);
        s0 += x0; s1 += x1; s2 += x2; s3 += x3;
    }
    #pragma unroll
    for (int o = 16; o > 0; o >>= 1) {
        s0 += __shfl_xor_sync(0xffffffffu, s0, o);
        s1 += __shfl_xor_sync(0xffffffffu, s1, o);
        s2 += __shfl_xor_sync(0xffffffffu, s2, o);
        s3 += __shfl_xor_sync(0xffffffffu, s3, o);
    }
    int head = lane >> 3;
    float sh = head == 0 ? s0 : head == 1 ? s1 : head == 2 ? s2 : s3;
    float inv = 1.0f / (sh + 1e-16f);

    // pass 2: weighted gather, 4 edges per iteration (MLP=8 H-vectors in flight)
    float acc[8] = {};
    int cb = lane * 8;
    int e = rs;
    for (; e + 4 <= re; e += 4) {
        int sa = csrc[e], sb = csrc[e + 1], sc = csrc[e + 2], sd = csrc[e + 3];
        float a0 = __ldg(ex + (e + 0) * 4 + head);
        float a1 = __ldg(ex + (e + 1) * 4 + head);
        float a2 = __ldg(ex + (e + 2) * 4 + head);
        float a3 = __ldg(ex + (e + 3) * 4 + head);
        const float4* p0 = (const float4*)(H + sa * DMODEL + cb);
        const float4* p1 = (const float4*)(H + sb * DMODEL + cb);
        const float4* p2 = (const float4*)(H + sc * DMODEL + cb);
        const float4* p3 = (const float4*)(H + sd * DMODEL + cb);
        float4 u0 = p0[0], v0 = p0[1];
        float4 u1 = p1[0], v1 = p1[1];
        float4 u2 = p2[0], v2 = p2[1];
        float4 u3 = p3[0], v3 = p3[1];
        a0 *= inv; a1 *= inv; a2 *= inv; a3 *= inv;
        acc[0] += a0 * u0.x + a1 * u1.x + a2 * u2.x + a3 * u3.x;
        acc[1] += a0 * u0.y + a1 * u1.y + a2 * u2.y + a3 * u3.y;
        acc[2] += a0 * u0.z + a1 * u1.z + a2 * u2.z + a3 * u3.z;
        acc[3] += a0 * u0.w + a1 * u1.w + a2 * u2.w + a3 * u3.w;
        acc[4] += a0 * v0.x + a1 * v1.x + a2 * v2.x + a3 * v3.x;
        acc[5] += a0 * v0.y + a1 * v1.y + a2 * v2.y + a3 * v3.y;
        acc[6] += a0 * v0.z + a1 * v1.z + a2 * v2.z + a3 * v3.z;
        acc[7] += a0 * v0.w + a1 * v1.w + a2 * v2.w + a3 * v3.w;
    }
    for (; e < re; e++) {
        int s = csrc[e];
        float alpha = __ldg(ex + e * 4 + head) * inv;
        const float4* hp = (const float4*)(H + s * DMODEL + cb);
        float4 h0 = hp[0], h1 = hp[1];
        acc[0] += alpha * h0.x; acc[1] += alpha * h0.y;
        acc[2] += alpha * h0.z; acc[3] += alpha * h0.w;
        acc[4] += alpha * h1.x; acc[5] += alpha * h1.y;
        acc[6] += alpha * h1.z; acc[7] += alpha * h1.w;
    }
    const float4* bp = (const float4*)(bias + cb);
    float4 b0 = bp[0], b1 = bp[1];
    r[0] = acc[0] + b0.x; r[1] = acc[1] + b0.y; r[2] = acc[2] + b0.z; r[3] = acc[3] + b0.w;
    r[4] = acc[4] + b1.x; r[5] = acc[5] + b1.y; r[6] = acc[6] + b1.z; r[7] = acc[7] + b1.w;
    #pragma unroll
    for (int i = 0; i < 8; i++) r[i] = r[i] > 0.0f ? r[i] : 0.0f;
}

__global__ void k_aggregate(const int* __restrict__ rowptr, const int* __restrict__ csrc,
                            const float* __restrict__ H, const float* __restrict__ aS,
                            const float* __restrict__ aD, const float* __restrict__ bias,
                            float* __restrict__ ex, float* __restrict__ out) {
    int node = (blockIdx.x * blockDim.x + threadIdx.x) >> 5;
    int lane = threadIdx.x & 31;
    if (node >= NNODE) return;
    float r[8];
    aggregate_node(node, lane, rowptr, csrc, H, aS, aD, bias, ex, r);
    float* op = out + node * DMODEL + lane * 8;
    *(float4*)op       = make_float4(r[0], r[1], r[2], r[3]);
    *(float4*)(op + 4) = make_float4(r[4], r[5], r[6], r[7]);
}

// ---------------- fused: layer-3 aggregate + dec_geo + fc_geo ------------------
__global__ void __launch_bounds__(256)
k_agg_final(const int* __restrict__ rowptr, const int* __restrict__ csrc,
            const float* __restrict__ H, const float* __restrict__ aS,
            const float* __restrict__ aD, const float* __restrict__ bias,
            float* __restrict__ ex,
            const float* __restrict__ Wg, const float* __restrict__ bg,
            const float* __restrict__ Wf, const float* __restrict__ bf,
            float* __restrict__ out) {
    __shared__ float sWg[128][FEAT];
    __shared__ float sx[8][DMODEL];
    __shared__ float sWf[FEAT * 5];

    int tid = threadIdx.x;
    int w = tid >> 5;
    int lane = tid & 31;
    int node = blockIdx.x * 8 + w;

    for (int i = tid; i < FEAT * 5; i += 256) sWf[i] = Wf[i];

    float r[8];
    aggregate_node(node, lane, rowptr, csrc, H, aS, aD, bias, ex, r);
    float* sxp = &sx[w][lane * 8];
    *(float4*)sxp       = make_float4(r[0], r[1], r[2], r[3]);
    *(float4*)(sxp + 4) = make_float4(r[4], r[5], r[6], r[7]);
    __syncthreads();

    float y0 = bg[lane], y1 = bg[lane + 32];
    #pragma unroll 1
    for (int kc = 0; kc < DMODEL; kc += 128) {
        #pragma unroll
        for (int t2 = 0; t2 < 8; t2++) {
            int idx = (tid + t2 * 256) * 4;
            *(float4*)&sWg[idx >> 6][idx & 63] =
                *(const float4*)(Wg + kc * FEAT + idx);
        }
        __syncthreads();
        #pragma unroll 4
        for (int k = 0; k < 128; k++) {
            float xv = sx[w][kc + k];
            y0 += xv * sWg[k][lane];
            y1 += xv * sWg[k][lane + 32];
        }
        __syncthreads();
    }
    y0 = y0 > 0.0f ? y0 : 0.0f;
    y1 = y1 > 0.0f ? y1 : 0.0f;

    float p[5];
    #pragma unroll
    for (int c = 0; c < 5; c++)
        p[c] = y0 * sWf[lane * 5 + c] + y1 * sWf[(lane + 32) * 5 + c];
    #pragma unroll
    for (int o = 16; o > 0; o >>= 1) {
        #pragma unroll
        for (int c = 0; c < 5; c++)
            p[c] += __shfl_xor_sync(0xffffffffu, p[c], o);
    }
    if (lane == 0) {
        #pragma unroll
        for (int c = 0; c < 5; c++)
            out[node * 5 + c] = p[c] + bf[c];
    }
}

// ---------------- host orchestration ------------------------------------------
extern "C" void kernel_launch(void* const* d_in, const int* in_sizes, int n_in,
                              void* d_out, int out_size) {
    const float* z     = (const float*)d_in[0];
    const int*   ei    = (const int*)d_in[1];
    const int*   batch = (const int*)d_in[2];
    int base = (in_sizes[3] == 1) ? 4 : 3;
    const float* W0  = (const float*)d_in[base + 0];
    const float* b0  = (const float*)d_in[base + 1];
    const float* W1  = (const float*)d_in[base + 2];
    const float* as1 = (const float*)d_in[base + 3];
    const float* ad1 = (const float*)d_in[base + 4];
    const float* bb1 = (const float*)d_in[base + 5];
    const float* W2  = (const float*)d_in[base + 6];
    const float* as2 = (const float*)d_in[base + 7];
    const float* ad2 = (const float*)d_in[base + 8];
    const float* bb2 = (const float*)d_in[base + 9];
    const float* W3  = (const float*)d_in[base + 10];
    const float* as3 = (const float*)d_in[base + 11];
    const float* ad3 = (const float*)d_in[base + 12];
    const float* bb3 = (const float*)d_in[base + 13];
    const float* Wg  = (const float*)d_in[base + 14];
    const float* bg  = (const float*)d_in[base + 15];
    const float* Wf  = (const float*)d_in[base + 16];
    const float* bf  = (const float*)d_in[base + 17];

    const int* srcArr = ei;
    const int* dstArr = ei + NEDGE;

    float *bufA, *bufB, *aS, *aD, *exB, *pgB;
    int *startsB, *degB, *rowptrB, *cursorB, *csrcB;
    cudaGetSymbolAddress((void**)&bufA, g_bufA);
    cudaGetSymbolAddress((void**)&bufB, g_bufB);
    cudaGetSymbolAddress((void**)&aS, g_as);
    cudaGetSymbolAddress((void**)&aD, g_ad);
    cudaGetSymbolAddress((void**)&exB, g_ex);
    cudaGetSymbolAddress((void**)&pgB, g_pg);
    cudaGetSymbolAddress((void**)&startsB, g_starts);
    cudaGetSymbolAddress((void**)&degB, g_deg);
    cudaGetSymbolAddress((void**)&rowptrB, g_rowptr);
    cudaGetSymbolAddress((void**)&cursorB, g_cursor);
    cudaGetSymbolAddress((void**)&csrcB, g_csrc);

    dim3 gemmGrid(NNODE / 128, 2);

    k_pro<<<NGRAPH + NBLK + EBLK, 256>>>(z, W0, b0, W1, pgB, batch, startsB,
                                         degB, dstArr);
    k_fill2<<<NBLK, 256>>>(degB, rowptrB, cursorB, csrcB);
    k_mid<<<WBLK + EBLK + NBLK, 256>>>(pgB, W1, batch, startsB, as1, ad1, bufB,
                                       aS, aD, srcArr, dstArr, cursorB, csrcB,
                                       degB);
    k_aggregate<<<WBLK, 256>>>(rowptrB, csrcB, bufB, aS, aD, bb1, exB, bufA);
    k_gemm_attn<<<gemmGrid, 256>>>(bufA, W2, as2, ad2, bufB, aS, aD);
    k_aggregate<<<WBLK, 256>>>(rowptrB, csrcB, bufB, aS, aD, bb2, exB, bufA);
    k_gemm_attn<<<gemmGrid, 256>>>(bufA, W3, as3, ad3, bufB, aS, aD);
    k_agg_final<<<WBLK, 256>>>(rowptrB, csrcB, bufB, aS, aD, bb3, exB,
                               Wg, bg, Wf, bf, (float*)d_out);
}

// round 10
// speedup vs baseline: 1.0698x; 1.0698x over previous
#include <cuda_runtime.h>
#include <math.h>
#include <stdint.h>

// ---------------- problem constants -----------------------------------------
#define NNODE 19200
#define NEDGE 230400
#define NGRAPH 128
#define LATENT 256
#define FEAT 64
#define HEADS 4
#define POS 180
#define DMODEL 256       // HEADS * FEAT
#define ETOT (NEDGE + NNODE)
#define NBLK 75          // NNODE / 256
#define EBLK 900         // NEDGE / 256
#define WBLK 2400        // NNODE / 8 (8 warps per block)

// ---------------- static device scratch --------------------------------------
__device__ __align__(16) float g_bufA[NNODE * DMODEL];
__device__ __align__(16) float g_bufB[NNODE * DMODEL];
__device__ __align__(16) float g_as[NNODE * HEADS];
__device__ __align__(16) float g_ad[NNODE * HEADS];
__device__ __align__(16) float g_ex[ETOT * HEADS];
__device__ __align__(16) float g_pg[NGRAPH * DMODEL];
__device__ int g_starts[NGRAPH];
__device__ int g_deg[NNODE];      // zero at load; re-zeroed each replay in k_mid
__device__ int g_rowptr[NNODE + 1];
__device__ int g_cursor[NNODE];
__device__ int g_csrc[ETOT];

// ---------------- fused prologue: x0pg | starts | hist -------------------------
__global__ void k_pro(const float* __restrict__ z, const float* __restrict__ W0,
                      const float* __restrict__ b0, const float* __restrict__ W1,
                      float* __restrict__ pg, const int* __restrict__ batch,
                      int* __restrict__ starts, int* __restrict__ deg,
                      const int* __restrict__ dst) {
    int b = blockIdx.x;
    int t = threadIdx.x;
    if (b < NGRAPH) {
        __shared__ float xs[FEAT];
        if (t < FEAT) {
            float acc = b0[t];
            const float* zr = z + b * LATENT;
            #pragma unroll 4
            for (int k = 0; k < LATENT; k++) acc += zr[k] * W0[k * FEAT + t];
            xs[t] = acc > 0.0f ? acc : 0.0f;
        }
        __syncthreads();
        float a = 0.0f;
        #pragma unroll
        for (int k = 0; k < FEAT; k++) a += xs[k] * W1[k * DMODEL + t];
        pg[b * DMODEL + t] = a;
    } else if (b < NGRAPH + NBLK) {
        int i = (b - NGRAPH) * 256 + t;
        int bb = batch[i];
        if (i == 0 || batch[i - 1] != bb) starts[bb] = i;
    } else {
        int e = (b - NGRAPH - NBLK) * 256 + t;
        atomicAdd(&deg[dst[e]], 1);
    }
}

// ---------------- CSR: prefix + local scan + self-loop fill --------------------
__global__ void k_fill2(const int* __restrict__ deg, int* __restrict__ rowptr,
                        int* __restrict__ cursor, int* __restrict__ csrc) {
    __shared__ int red[256];
    __shared__ int s[256];
    int t = threadIdx.x;
    int b = blockIdx.x;
    int lim = b * 256;
    int sum = 0;
    for (int i = t; i < lim; i += 256) sum += deg[i] + 1;   // +1 self loop
    red[t] = sum;
    __syncthreads();
    for (int off = 128; off > 0; off >>= 1) {
        if (t < off) red[t] += red[t + off];
        __syncthreads();
    }
    int node = lim + t;
    int d = deg[node] + 1;
    s[t] = d;
    __syncthreads();
    for (int off = 1; off < 256; off <<= 1) {
        int u = (t >= off) ? s[t - off] : 0;
        __syncthreads();
        s[t] += u;
        __syncthreads();
    }
    int r = red[0] + s[t] - d;
    rowptr[node] = r;
    csrc[r] = node;                           // self loop first
    cursor[node] = r + 1;
    if (node == NNODE - 1) rowptr[NNODE] = red[0] + s[t];
}

// ---------------- fused: h1+attn | CSR scatter | deg re-zero --------------------
__global__ void k_mid(const float* __restrict__ pg, const float* __restrict__ W1,
                      const int* __restrict__ batch, const int* __restrict__ starts,
                      const float* __restrict__ attS, const float* __restrict__ attD,
                      float* __restrict__ H, float* __restrict__ aS,
                      float* __restrict__ aD,
                      const int* __restrict__ src, const int* __restrict__ dst,
                      int* __restrict__ cursor, int* __restrict__ csrc,
                      int* __restrict__ deg) {
    int b = blockIdx.x;
    int tid = threadIdx.x;
    if (b >= WBLK + EBLK) {
        deg[(b - WBLK - EBLK) * 256 + tid] = 0;
        return;
    }
    if (b >= WBLK) {
        int e = (b - WBLK) * 256 + tid;
        int p = atomicAdd(&cursor[dst[e]], 1);
        csrc[p] = src[e];
        return;
    }
    __shared__ float sS[DMODEL], sD[DMODEL];
    if (tid < DMODEL) { sS[tid] = attS[tid]; sD[tid] = attD[tid]; }
    __syncthreads();
    int node = b * 8 + (tid >> 5);
    int lane = tid & 31;
    int g = batch[node];
    int order = node - starts[g];
    int c0 = lane * 8;
    const float4* pgr = (const float4*)(pg + g * DMODEL + c0);
    const float4* w1r = (const float4*)(W1 + (FEAT + order) * DMODEL + c0);
    float4 p0 = pgr[0], p1 = pgr[1];
    float4 w0 = w1r[0], w1v = w1r[1];
    float h[8];
    h[0] = p0.x + w0.x; h[1] = p0.y + w0.y; h[2] = p0.z + w0.z; h[3] = p0.w + w0.w;
    h[4] = p1.x + w1v.x; h[5] = p1.y + w1v.y; h[6] = p1.z + w1v.z; h[7] = p1.w + w1v.w;
    float* hr = H + node * DMODEL + c0;
    *(float4*)hr       = make_float4(h[0], h[1], h[2], h[3]);
    *(float4*)(hr + 4) = make_float4(h[4], h[5], h[6], h[7]);
    float pS = 0.0f, pD = 0.0f;
    #pragma unroll
    for (int j = 0; j < 8; j++) { pS += h[j] * sS[c0 + j]; pD += h[j] * sD[c0 + j]; }
    pS += __shfl_xor_sync(0xffffffffu, pS, 1);
    pS += __shfl_xor_sync(0xffffffffu, pS, 2);
    pS += __shfl_xor_sync(0xffffffffu, pS, 4);
    pD += __shfl_xor_sync(0xffffffffu, pD, 1);
    pD += __shfl_xor_sync(0xffffffffu, pD, 2);
    pD += __shfl_xor_sync(0xffffffffu, pD, 4);
    if ((lane & 7) == 0) {
        int hd = lane >> 3;
        aS[node * 4 + hd] = pS;
        aD[node * 4 + hd] = pD;
    }
}

// ---------------- tf32 tensor-core GEMM + fused attention logits ---------------
// occupancy 2 to fix wave quantization (300 blocks on 148 SMs).
#define SMS 136
__device__ __forceinline__ uint32_t f2tf32(float v) {
    uint32_t r;
    asm("cvt.rna.tf32.f32 %0, %1;" : "=r"(r) : "f"(v));
    return r;
}
__device__ __forceinline__ void mma_tf32(float* c, uint32_t a0, uint32_t a1,
                                         uint32_t a2, uint32_t a3,
                                         uint32_t b0, uint32_t b1) {
    asm volatile(
        "mma.sync.aligned.m16n8k8.row.col.f32.tf32.tf32.f32 "
        "{%0,%1,%2,%3}, {%4,%5,%6,%7}, {%8,%9}, {%0,%1,%2,%3};"
        : "+f"(c[0]), "+f"(c[1]), "+f"(c[2]), "+f"(c[3])
        : "r"(a0), "r"(a1), "r"(a2), "r"(a3), "r"(b0), "r"(b1));
}

__global__ void __launch_bounds__(256, 2)
k_gemm_attn(const float* __restrict__ X, const float* __restrict__ W,
            const float* __restrict__ attS, const float* __restrict__ attD,
            float* __restrict__ C, float* __restrict__ aS, float* __restrict__ aD) {
    __shared__ uint32_t As[32][SMS];
    __shared__ uint32_t Bs[32][SMS];
    __shared__ float sS[128], sD[128];
    __shared__ float sPS[128][2], sPD[128][2];

    int tid = threadIdx.x;
    int lane = tid & 31;
    int w = tid >> 5;
    int wm = w & 1, wn = w >> 1;
    int r0 = blockIdx.x * 128;
    int c0 = blockIdx.y * 128;

    if (tid < 128) { sS[tid] = attS[c0 + tid]; sD[tid] = attD[c0 + tid]; }
    {
        int rr = tid >> 1, hh = tid & 1;
        sPS[rr][hh] = 0.0f;
        sPD[rr][hh] = 0.0f;
    }

    float acc[4][4][4];
    #pragma unroll
    for (int i = 0; i < 4; i++)
        #pragma unroll
        for (int j = 0; j < 4; j++)
            #pragma unroll
            for (int q = 0; q < 4; q++) acc[i][j][q] = 0.0f;

    int am = tid >> 1;
    int ak = (tid & 1) * 16;
    int bkr = tid >> 3;
    int bn = (tid & 7) * 16;

    #pragma unroll 1
    for (int kc = 0; kc < DMODEL; kc += 32) {
        const float4* ap = (const float4*)(X + (r0 + am) * DMODEL + kc + ak);
        #pragma unroll
        for (int q = 0; q < 4; q++) {
            float4 v = ap[q];
            As[ak + q * 4 + 0][am] = f2tf32(v.x);
            As[ak + q * 4 + 1][am] = f2tf32(v.y);
            As[ak + q * 4 + 2][am] = f2tf32(v.z);
            As[ak + q * 4 + 3][am] = f2tf32(v.w);
        }
        const float4* bp = (const float4*)(W + (kc + bkr) * DMODEL + c0 + bn);
        #pragma unroll
        for (int q = 0; q < 4; q++) {
            float4 v = bp[q];
            uint4 u;
            u.x = f2tf32(v.x); u.y = f2tf32(v.y);
            u.z = f2tf32(v.z); u.w = f2tf32(v.w);
            *(uint4*)&Bs[bkr][bn + q * 4] = u;
        }
        __syncthreads();

        #pragma unroll
        for (int kk = 0; kk < 4; kk++) {
            int kb = kk * 8;
            int klo = kb + (lane & 3), khi = klo + 4;
            uint32_t afr[4][4], bfr[4][2];
            #pragma unroll
            for (int mt = 0; mt < 4; mt++) {
                int m = wm * 64 + mt * 16 + (lane >> 2);
                afr[mt][0] = As[klo][m];
                afr[mt][1] = As[klo][m + 8];
                afr[mt][2] = As[khi][m];
                afr[mt][3] = As[khi][m + 8];
            }
            #pragma unroll
            for (int nt = 0; nt < 4; nt++) {
                int n = wn * 32 + nt * 8 + (lane >> 2);
                bfr[nt][0] = Bs[klo][n];
                bfr[nt][1] = Bs[khi][n];
            }
            #pragma unroll
            for (int mt = 0; mt < 4; mt++)
                #pragma unroll
                for (int nt = 0; nt < 4; nt++)
                    mma_tf32(acc[mt][nt], afr[mt][0], afr[mt][1], afr[mt][2],
                             afr[mt][3], bfr[nt][0], bfr[nt][1]);
        }
        __syncthreads();
    }

    int hb = wn >> 1;
    #pragma unroll
    for (int mt = 0; mt < 4; mt++) {
        int rowA = wm * 64 + mt * 16 + (lane >> 2);
        int rowB = rowA + 8;
        float pSa = 0.0f, pDa = 0.0f, pSb = 0.0f, pDb = 0.0f;
        #pragma unroll
        for (int nt = 0; nt < 4; nt++) {
            int lc = wn * 32 + nt * 8 + 2 * (lane & 3);
            float s0 = sS[lc], s1 = sS[lc + 1];
            float d0 = sD[lc], d1 = sD[lc + 1];
            float* a = acc[mt][nt];
            pSa += a[0] * s0 + a[1] * s1;
            pDa += a[0] * d0 + a[1] * d1;
            pSb += a[2] * s0 + a[3] * s1;
            pDb += a[2] * d0 + a[3] * d1;
            float* cpA = C + (r0 + rowA) * DMODEL + c0 + lc;
            float* cpB = C + (r0 + rowB) * DMODEL + c0 + lc;
            *(float2*)cpA = make_float2(a[0], a[1]);
            *(float2*)cpB = make_float2(a[2], a[3]);
        }
        pSa += __shfl_xor_sync(0xffffffffu, pSa, 1);
        pSa += __shfl_xor_sync(0xffffffffu, pSa, 2);
        pDa += __shfl_xor_sync(0xffffffffu, pDa, 1);
        pDa += __shfl_xor_sync(0xffffffffu, pDa, 2);
        pSb += __shfl_xor_sync(0xffffffffu, pSb, 1);
        pSb += __shfl_xor_sync(0xffffffffu, pSb, 2);
        pDb += __shfl_xor_sync(0xffffffffu, pDb, 1);
        pDb += __shfl_xor_sync(0xffffffffu, pDb, 2);
        if ((lane & 3) == 0) {
            atomicAdd(&sPS[rowA][hb], pSa);
            atomicAdd(&sPD[rowA][hb], pDa);
            atomicAdd(&sPS[rowB][hb], pSb);
            atomicAdd(&sPD[rowB][hb], pDb);
        }
    }
    __syncthreads();
    {
        int rr = tid >> 1, hh = tid & 1;
        int node = r0 + rr;
        int head = blockIdx.y * 2 + hh;
        aS[node * 4 + head] = sPS[rr][hh];
        aD[node * 4 + head] = sPD[rr][hh];
    }
}

// ---------------- segment softmax + weighted aggregate (device body) ----------
// R8 scalar pass-2 form (R9 unroll regressed: kernel is L1-throughput bound,
// ILP only cost occupancy).
__device__ __forceinline__ float lrelu(float v) { return v > 0.0f ? v : 0.2f * v; }

__device__ __forceinline__ void aggregate_node(
    int node, int lane, const int* __restrict__ rowptr, const int* __restrict__ csrc,
    const float* __restrict__ H, const float* __restrict__ aS,
    const float* __restrict__ aD, const float* __restrict__ bias,
    float* __restrict__ ex, float r[8]) {
    int rs = rowptr[node], re = rowptr[node + 1];
    float4 ad = *(const float4*)(aD + node * 4);

    // pass 1: logits -> ex (raw), track max
    float m0 = -1e30f, m1 = -1e30f, m2 = -1e30f, m3 = -1e30f;
    for (int e = rs + lane; e < re; e += 32) {
        int s = csrc[e];
        float4 as = *(const float4*)(aS + s * 4);
        float e0 = lrelu(as.x + ad.x);
        float e1 = lrelu(as.y + ad.y);
        float e2 = lrelu(as.z + ad.z);
        float e3 = lrelu(as.w + ad.w);
        *(float4*)(ex + e * 4) = make_float4(e0, e1, e2, e3);
        m0 = fmaxf(m0, e0); m1 = fmaxf(m1, e1);
        m2 = fmaxf(m2, e2); m3 = fmaxf(m3, e3);
    }
    #pragma unroll
    for (int o = 16; o > 0; o >>= 1) {
        m0 = fmaxf(m0, __shfl_xor_sync(0xffffffffu, m0, o));
        m1 = fmaxf(m1, __shfl_xor_sync(0xffffffffu, m1, o));
        m2 = fmaxf(m2, __shfl_xor_sync(0xffffffffu, m2, o));
        m3 = fmaxf(m3, __shfl_xor_sync(0xffffffffu, m3, o));
    }
    // pass 1b: exp over L1-hot ex, write back, sum
    float s0 = 0, s1 = 0, s2 = 0, s3 = 0;
    for (int e = rs + lane; e < re; e += 32) {
        float4 ev = *(const float4*)(ex + e * 4);
        float x0 = expf(ev.x - m0);
        float x1 = expf(ev.y - m1);
        float x2 = expf(ev.z - m2);
        float x3 = expf(ev.w - m3);
        *(float4*)(ex + e * 4) = make_float4(x0, x1, x2, x3);
        s0 += x0; s1 += x1; s2 += x2; s3 += x3;
    }
    #pragma unroll
    for (int o = 16; o > 0; o >>= 1) {
        s0 += __shfl_xor_sync(0xffffffffu, s0, o);
        s1 += __shfl_xor_sync(0xffffffffu, s1, o);
        s2 += __shfl_xor_sync(0xffffffffu, s2, o);
        s3 += __shfl_xor_sync(0xffffffffu, s3, o);
    }
    int head = lane >> 3;
    float sh = head == 0 ? s0 : head == 1 ? s1 : head == 2 ? s2 : s3;
    float inv = 1.0f / (sh + 1e-16f);

    // pass 2: scalar weighted gather, one edge per iteration (index prefetch)
    float acc[8] = {};
    int cb = lane * 8;
    int sNext = csrc[rs];
    for (int e = rs; e < re; e++) {
        int s = sNext;
        if (e + 1 < re) sNext = csrc[e + 1];
        float alpha = __ldg(ex + e * 4 + head) * inv;
        const float4* hp = (const float4*)(H + s * DMODEL + cb);
        float4 h0 = hp[0], h1 = hp[1];
        acc[0] += alpha * h0.x; acc[1] += alpha * h0.y;
        acc[2] += alpha * h0.z; acc[3] += alpha * h0.w;
        acc[4] += alpha * h1.x; acc[5] += alpha * h1.y;
        acc[6] += alpha * h1.z; acc[7] += alpha * h1.w;
    }
    const float4* bp = (const float4*)(bias + cb);
    float4 b0 = bp[0], b1 = bp[1];
    r[0] = acc[0] + b0.x; r[1] = acc[1] + b0.y; r[2] = acc[2] + b0.z; r[3] = acc[3] + b0.w;
    r[4] = acc[4] + b1.x; r[5] = acc[5] + b1.y; r[6] = acc[6] + b1.z; r[7] = acc[7] + b1.w;
    #pragma unroll
    for (int i = 0; i < 8; i++) r[i] = r[i] > 0.0f ? r[i] : 0.0f;
}

__global__ void k_aggregate(const int* __restrict__ rowptr, const int* __restrict__ csrc,
                            const float* __restrict__ H, const float* __restrict__ aS,
                            const float* __restrict__ aD, const float* __restrict__ bias,
                            float* __restrict__ ex, float* __restrict__ out) {
    int node = (blockIdx.x * blockDim.x + threadIdx.x) >> 5;
    int lane = threadIdx.x & 31;
    if (node >= NNODE) return;
    float r[8];
    aggregate_node(node, lane, rowptr, csrc, H, aS, aD, bias, ex, r);
    float* op = out + node * DMODEL + lane * 8;
    *(float4*)op       = make_float4(r[0], r[1], r[2], r[3]);
    *(float4*)(op + 4) = make_float4(r[4], r[5], r[6], r[7]);
}

// ---------------- fused: layer-3 aggregate + dec_geo + fc_geo ------------------
__global__ void __launch_bounds__(256)
k_agg_final(const int* __restrict__ rowptr, const int* __restrict__ csrc,
            const float* __restrict__ H, const float* __restrict__ aS,
            const float* __restrict__ aD, const float* __restrict__ bias,
            float* __restrict__ ex,
            const float* __restrict__ Wg, const float* __restrict__ bg,
            const float* __restrict__ Wf, const float* __restrict__ bf,
            float* __restrict__ out) {
    __shared__ float sWg[128][FEAT];
    __shared__ float sx[8][DMODEL];
    __shared__ float sWf[FEAT * 5];

    int tid = threadIdx.x;
    int w = tid >> 5;
    int lane = tid & 31;
    int node = blockIdx.x * 8 + w;

    for (int i = tid; i < FEAT * 5; i += 256) sWf[i] = Wf[i];

    float r[8];
    aggregate_node(node, lane, rowptr, csrc, H, aS, aD, bias, ex, r);
    float* sxp = &sx[w][lane * 8];
    *(float4*)sxp       = make_float4(r[0], r[1], r[2], r[3]);
    *(float4*)(sxp + 4) = make_float4(r[4], r[5], r[6], r[7]);
    __syncthreads();

    float y0 = bg[lane], y1 = bg[lane + 32];
    #pragma unroll 1
    for (int kc = 0; kc < DMODEL; kc += 128) {
        #pragma unroll
        for (int t2 = 0; t2 < 8; t2++) {
            int idx = (tid + t2 * 256) * 4;
            *(float4*)&sWg[idx >> 6][idx & 63] =
                *(const float4*)(Wg + kc * FEAT + idx);
        }
        __syncthreads();
        #pragma unroll 4
        for (int k = 0; k < 128; k++) {
            float xv = sx[w][kc + k];
            y0 += xv * sWg[k][lane];
            y1 += xv * sWg[k][lane + 32];
        }
        __syncthreads();
    }
    y0 = y0 > 0.0f ? y0 : 0.0f;
    y1 = y1 > 0.0f ? y1 : 0.0f;

    float p[5];
    #pragma unroll
    for (int c = 0; c < 5; c++)
        p[c] = y0 * sWf[lane * 5 + c] + y1 * sWf[(lane + 32) * 5 + c];
    #pragma unroll
    for (int o = 16; o > 0; o >>= 1) {
        #pragma unroll
        for (int c = 0; c < 5; c++)
            p[c] += __shfl_xor_sync(0xffffffffu, p[c], o);
    }
    if (lane == 0) {
        #pragma unroll
        for (int c = 0; c < 5; c++)
            out[node * 5 + c] = p[c] + bf[c];
    }
}

// ---------------- host orchestration ------------------------------------------
extern "C" void kernel_launch(void* const* d_in, const int* in_sizes, int n_in,
                              void* d_out, int out_size) {
    const float* z     = (const float*)d_in[0];
    const int*   ei    = (const int*)d_in[1];
    const int*   batch = (const int*)d_in[2];
    int base = (in_sizes[3] == 1) ? 4 : 3;
    const float* W0  = (const float*)d_in[base + 0];
    const float* b0  = (const float*)d_in[base + 1];
    const float* W1  = (const float*)d_in[base + 2];
    const float* as1 = (const float*)d_in[base + 3];
    const float* ad1 = (const float*)d_in[base + 4];
    const float* bb1 = (const float*)d_in[base + 5];
    const float* W2  = (const float*)d_in[base + 6];
    const float* as2 = (const float*)d_in[base + 7];
    const float* ad2 = (const float*)d_in[base + 8];
    const float* bb2 = (const float*)d_in[base + 9];
    const float* W3  = (const float*)d_in[base + 10];
    const float* as3 = (const float*)d_in[base + 11];
    const float* ad3 = (const float*)d_in[base + 12];
    const float* bb3 = (const float*)d_in[base + 13];
    const float* Wg  = (const float*)d_in[base + 14];
    const float* bg  = (const float*)d_in[base + 15];
    const float* Wf  = (const float*)d_in[base + 16];
    const float* bf  = (const float*)d_in[base + 17];

    const int* srcArr = ei;
    const int* dstArr = ei + NEDGE;

    float *bufA, *bufB, *aS, *aD, *exB, *pgB;
    int *startsB, *degB, *rowptrB, *cursorB, *csrcB;
    cudaGetSymbolAddress((void**)&bufA, g_bufA);
    cudaGetSymbolAddress((void**)&bufB, g_bufB);
    cudaGetSymbolAddress((void**)&aS, g_as);
    cudaGetSymbolAddress((void**)&aD, g_ad);
    cudaGetSymbolAddress((void**)&exB, g_ex);
    cudaGetSymbolAddress((void**)&pgB, g_pg);
    cudaGetSymbolAddress((void**)&startsB, g_starts);
    cudaGetSymbolAddress((void**)&degB, g_deg);
    cudaGetSymbolAddress((void**)&rowptrB, g_rowptr);
    cudaGetSymbolAddress((void**)&cursorB, g_cursor);
    cudaGetSymbolAddress((void**)&csrcB, g_csrc);

    dim3 gemmGrid(NNODE / 128, 2);

    k_pro<<<NGRAPH + NBLK + EBLK, 256>>>(z, W0, b0, W1, pgB, batch, startsB,
                                         degB, dstArr);
    k_fill2<<<NBLK, 256>>>(degB, rowptrB, cursorB, csrcB);
    k_mid<<<WBLK + EBLK + NBLK, 256>>>(pgB, W1, batch, startsB, as1, ad1, bufB,
                                       aS, aD, srcArr, dstArr, cursorB, csrcB,
                                       degB);
    k_aggregate<<<WBLK, 256>>>(rowptrB, csrcB, bufB, aS, aD, bb1, exB, bufA);
    k_gemm_attn<<<gemmGrid, 256>>>(bufA, W2, as2, ad2, bufB, aS, aD);
    k_aggregate<<<WBLK, 256>>>(rowptrB, csrcB, bufB, aS, aD, bb2, exB, bufA);
    k_gemm_attn<<<gemmGrid, 256>>>(bufA, W3, as3, ad3, bufB, aS, aD);
    k_agg_final<<<WBLK, 256>>>(rowptrB, csrcB, bufB, aS, aD, bb3, exB,
                               Wg, bg, Wf, bf, (float*)d_out);
}

// round 11
// speedup vs baseline: 1.0884x; 1.0174x over previous
#include <cuda_runtime.h>
#include <math.h>
#include <stdint.h>

// ---------------- problem constants -----------------------------------------
#define NNODE 19200
#define NEDGE 230400
#define NGRAPH 128
#define LATENT 256
#define FEAT 64
#define HEADS 4
#define POS 180
#define DMODEL 256       // HEADS * FEAT
#define ETOT (NEDGE + NNODE)
#define NBLK 75          // NNODE / 256
#define EBLK 900         // NEDGE / 256
#define WBLK 2400        // NNODE / 8 (8 warps per block)

// ---------------- static device scratch --------------------------------------
__device__ __align__(16) float g_bufA[NNODE * DMODEL];
__device__ __align__(16) float g_bufB[NNODE * DMODEL];
__device__ __align__(16) float g_as[NNODE * HEADS];
__device__ __align__(16) float g_ad[NNODE * HEADS];
__device__ __align__(16) float g_ex[ETOT * HEADS];
__device__ __align__(16) float g_pg[NGRAPH * DMODEL];
__device__ __align__(16) float g_maxS[3][4];   // per-layer global aS max (slots)
__device__ int g_starts[NGRAPH];
__device__ int g_deg[NNODE];      // zero at load; re-zeroed each replay in k_mid
__device__ int g_rowptr[NNODE + 1];
__device__ int g_cursor[NNODE];
__device__ int g_csrc[ETOT];

__device__ __forceinline__ void atomicMaxF(float* a, float v) {
    if (v >= 0.0f) atomicMax((int*)a, __float_as_int(v));
    else           atomicMin((unsigned int*)a, __float_as_uint(v));
}

// ---------------- fused prologue: x0pg | starts | hist -------------------------
__global__ void k_pro(const float* __restrict__ z, const float* __restrict__ W0,
                      const float* __restrict__ b0, const float* __restrict__ W1,
                      float* __restrict__ pg, const int* __restrict__ batch,
                      int* __restrict__ starts, int* __restrict__ deg,
                      const int* __restrict__ dst) {
    int b = blockIdx.x;
    int t = threadIdx.x;
    if (b < NGRAPH) {
        __shared__ float xs[FEAT];
        if (t < FEAT) {
            float acc = b0[t];
            const float* zr = z + b * LATENT;
            #pragma unroll 4
            for (int k = 0; k < LATENT; k++) acc += zr[k] * W0[k * FEAT + t];
            xs[t] = acc > 0.0f ? acc : 0.0f;
        }
        __syncthreads();
        float a = 0.0f;
        #pragma unroll
        for (int k = 0; k < FEAT; k++) a += xs[k] * W1[k * DMODEL + t];
        pg[b * DMODEL + t] = a;
    } else if (b < NGRAPH + NBLK) {
        int i = (b - NGRAPH) * 256 + t;
        int bb = batch[i];
        if (i == 0 || batch[i - 1] != bb) starts[bb] = i;
    } else {
        int e = (b - NGRAPH - NBLK) * 256 + t;
        atomicAdd(&deg[dst[e]], 1);
    }
}

// ---------------- CSR: prefix + local scan + self-loop fill + maxS init --------
__global__ void k_fill2(const int* __restrict__ deg, int* __restrict__ rowptr,
                        int* __restrict__ cursor, int* __restrict__ csrc,
                        float* __restrict__ maxS) {
    __shared__ int red[256];
    __shared__ int s[256];
    int t = threadIdx.x;
    int b = blockIdx.x;
    if (b == 0 && t < 12) maxS[t] = __int_as_float(0xff800000);  // -inf, 3 slots
    int lim = b * 256;
    int sum = 0;
    for (int i = t; i < lim; i += 256) sum += deg[i] + 1;   // +1 self loop
    red[t] = sum;
    __syncthreads();
    for (int off = 128; off > 0; off >>= 1) {
        if (t < off) red[t] += red[t + off];
        __syncthreads();
    }
    int node = lim + t;
    int d = deg[node] + 1;
    s[t] = d;
    __syncthreads();
    for (int off = 1; off < 256; off <<= 1) {
        int u = (t >= off) ? s[t - off] : 0;
        __syncthreads();
        s[t] += u;
        __syncthreads();
    }
    int r = red[0] + s[t] - d;
    rowptr[node] = r;
    csrc[r] = node;                           // self loop first
    cursor[node] = r + 1;
    if (node == NNODE - 1) rowptr[NNODE] = red[0] + s[t];
}

// ---------------- fused: h1+attn | CSR scatter | deg re-zero --------------------
__global__ void k_mid(const float* __restrict__ pg, const float* __restrict__ W1,
                      const int* __restrict__ batch, const int* __restrict__ starts,
                      const float* __restrict__ attS, const float* __restrict__ attD,
                      float* __restrict__ H, float* __restrict__ aS,
                      float* __restrict__ aD,
                      const int* __restrict__ src, const int* __restrict__ dst,
                      int* __restrict__ cursor, int* __restrict__ csrc,
                      int* __restrict__ deg, float* __restrict__ maxS) {
    int b = blockIdx.x;
    int tid = threadIdx.x;
    if (b >= WBLK + EBLK) {
        deg[(b - WBLK - EBLK) * 256 + tid] = 0;
        return;
    }
    if (b >= WBLK) {
        int e = (b - WBLK) * 256 + tid;
        int p = atomicAdd(&cursor[dst[e]], 1);
        csrc[p] = src[e];
        return;
    }
    __shared__ float sS[DMODEL], sD[DMODEL];
    __shared__ float sMax[4];
    if (tid < DMODEL) { sS[tid] = attS[tid]; sD[tid] = attD[tid]; }
    if (tid < 4) sMax[tid] = __int_as_float(0xff800000);
    __syncthreads();
    int node = b * 8 + (tid >> 5);
    int lane = tid & 31;
    int g = batch[node];
    int order = node - starts[g];
    int c0 = lane * 8;
    const float4* pgr = (const float4*)(pg + g * DMODEL + c0);
    const float4* w1r = (const float4*)(W1 + (FEAT + order) * DMODEL + c0);
    float4 p0 = pgr[0], p1 = pgr[1];
    float4 w0 = w1r[0], w1v = w1r[1];
    float h[8];
    h[0] = p0.x + w0.x; h[1] = p0.y + w0.y; h[2] = p0.z + w0.z; h[3] = p0.w + w0.w;
    h[4] = p1.x + w1v.x; h[5] = p1.y + w1v.y; h[6] = p1.z + w1v.z; h[7] = p1.w + w1v.w;
    float* hr = H + node * DMODEL + c0;
    *(float4*)hr       = make_float4(h[0], h[1], h[2], h[3]);
    *(float4*)(hr + 4) = make_float4(h[4], h[5], h[6], h[7]);
    float pS = 0.0f, pD = 0.0f;
    #pragma unroll
    for (int j = 0; j < 8; j++) { pS += h[j] * sS[c0 + j]; pD += h[j] * sD[c0 + j]; }
    pS += __shfl_xor_sync(0xffffffffu, pS, 1);
    pS += __shfl_xor_sync(0xffffffffu, pS, 2);
    pS += __shfl_xor_sync(0xffffffffu, pS, 4);
    pD += __shfl_xor_sync(0xffffffffu, pD, 1);
    pD += __shfl_xor_sync(0xffffffffu, pD, 2);
    pD += __shfl_xor_sync(0xffffffffu, pD, 4);
    if ((lane & 7) == 0) {
        int hd = lane >> 3;
        aS[node * 4 + hd] = pS;
        aD[node * 4 + hd] = pD;
        atomicMaxF(&sMax[hd], pS);
    }
    __syncthreads();
    if (tid < 4) atomicMaxF(&maxS[tid], sMax[tid]);
}

// ---------------- tf32 tensor-core GEMM + fused attention logits ---------------
#define SMS 136
__device__ __forceinline__ uint32_t f2tf32(float v) {
    uint32_t r;
    asm("cvt.rna.tf32.f32 %0, %1;" : "=r"(r) : "f"(v));
    return r;
}
__device__ __forceinline__ void mma_tf32(float* c, uint32_t a0, uint32_t a1,
                                         uint32_t a2, uint32_t a3,
                                         uint32_t b0, uint32_t b1) {
    asm volatile(
        "mma.sync.aligned.m16n8k8.row.col.f32.tf32.tf32.f32 "
        "{%0,%1,%2,%3}, {%4,%5,%6,%7}, {%8,%9}, {%0,%1,%2,%3};"
        : "+f"(c[0]), "+f"(c[1]), "+f"(c[2]), "+f"(c[3])
        : "r"(a0), "r"(a1), "r"(a2), "r"(a3), "r"(b0), "r"(b1));
}

__global__ void __launch_bounds__(256, 2)
k_gemm_attn(const float* __restrict__ X, const float* __restrict__ W,
            const float* __restrict__ attS, const float* __restrict__ attD,
            float* __restrict__ C, float* __restrict__ aS, float* __restrict__ aD,
            float* __restrict__ maxS) {
    __shared__ uint32_t As[32][SMS];
    __shared__ uint32_t Bs[32][SMS];
    __shared__ float sS[128], sD[128];
    __shared__ float sPS[128][2], sPD[128][2];
    __shared__ float sMax[2];

    int tid = threadIdx.x;
    int lane = tid & 31;
    int w = tid >> 5;
    int wm = w & 1, wn = w >> 1;
    int r0 = blockIdx.x * 128;
    int c0 = blockIdx.y * 128;

    if (tid < 128) { sS[tid] = attS[c0 + tid]; sD[tid] = attD[c0 + tid]; }
    if (tid < 2) sMax[tid] = __int_as_float(0xff800000);
    {
        int rr = tid >> 1, hh = tid & 1;
        sPS[rr][hh] = 0.0f;
        sPD[rr][hh] = 0.0f;
    }

    float acc[4][4][4];
    #pragma unroll
    for (int i = 0; i < 4; i++)
        #pragma unroll
        for (int j = 0; j < 4; j++)
            #pragma unroll
            for (int q = 0; q < 4; q++) acc[i][j][q] = 0.0f;

    int am = tid >> 1;
    int ak = (tid & 1) * 16;
    int bkr = tid >> 3;
    int bn = (tid & 7) * 16;

    #pragma unroll 1
    for (int kc = 0; kc < DMODEL; kc += 32) {
        const float4* ap = (const float4*)(X + (r0 + am) * DMODEL + kc + ak);
        #pragma unroll
        for (int q = 0; q < 4; q++) {
            float4 v = ap[q];
            As[ak + q * 4 + 0][am] = f2tf32(v.x);
            As[ak + q * 4 + 1][am] = f2tf32(v.y);
            As[ak + q * 4 + 2][am] = f2tf32(v.z);
            As[ak + q * 4 + 3][am] = f2tf32(v.w);
        }
        const float4* bp = (const float4*)(W + (kc + bkr) * DMODEL + c0 + bn);
        #pragma unroll
        for (int q = 0; q < 4; q++) {
            float4 v = bp[q];
            uint4 u;
            u.x = f2tf32(v.x); u.y = f2tf32(v.y);
            u.z = f2tf32(v.z); u.w = f2tf32(v.w);
            *(uint4*)&Bs[bkr][bn + q * 4] = u;
        }
        __syncthreads();

        #pragma unroll
        for (int kk = 0; kk < 4; kk++) {
            int kb = kk * 8;
            int klo = kb + (lane & 3), khi = klo + 4;
            uint32_t afr[4][4], bfr[4][2];
            #pragma unroll
            for (int mt = 0; mt < 4; mt++) {
                int m = wm * 64 + mt * 16 + (lane >> 2);
                afr[mt][0] = As[klo][m];
                afr[mt][1] = As[klo][m + 8];
                afr[mt][2] = As[khi][m];
                afr[mt][3] = As[khi][m + 8];
            }
            #pragma unroll
            for (int nt = 0; nt < 4; nt++) {
                int n = wn * 32 + nt * 8 + (lane >> 2);
                bfr[nt][0] = Bs[klo][n];
                bfr[nt][1] = Bs[khi][n];
            }
            #pragma unroll
            for (int mt = 0; mt < 4; mt++)
                #pragma unroll
                for (int nt = 0; nt < 4; nt++)
                    mma_tf32(acc[mt][nt], afr[mt][0], afr[mt][1], afr[mt][2],
                             afr[mt][3], bfr[nt][0], bfr[nt][1]);
        }
        __syncthreads();
    }

    int hb = wn >> 1;
    #pragma unroll
    for (int mt = 0; mt < 4; mt++) {
        int rowA = wm * 64 + mt * 16 + (lane >> 2);
        int rowB = rowA + 8;
        float pSa = 0.0f, pDa = 0.0f, pSb = 0.0f, pDb = 0.0f;
        #pragma unroll
        for (int nt = 0; nt < 4; nt++) {
            int lc = wn * 32 + nt * 8 + 2 * (lane & 3);
            float s0 = sS[lc], s1 = sS[lc + 1];
            float d0 = sD[lc], d1 = sD[lc + 1];
            float* a = acc[mt][nt];
            pSa += a[0] * s0 + a[1] * s1;
            pDa += a[0] * d0 + a[1] * d1;
            pSb += a[2] * s0 + a[3] * s1;
            pDb += a[2] * d0 + a[3] * d1;
            float* cpA = C + (r0 + rowA) * DMODEL + c0 + lc;
            float* cpB = C + (r0 + rowB) * DMODEL + c0 + lc;
            *(float2*)cpA = make_float2(a[0], a[1]);
            *(float2*)cpB = make_float2(a[2], a[3]);
        }
        pSa += __shfl_xor_sync(0xffffffffu, pSa, 1);
        pSa += __shfl_xor_sync(0xffffffffu, pSa, 2);
        pDa += __shfl_xor_sync(0xffffffffu, pDa, 1);
        pDa += __shfl_xor_sync(0xffffffffu, pDa, 2);
        pSb += __shfl_xor_sync(0xffffffffu, pSb, 1);
        pSb += __shfl_xor_sync(0xffffffffu, pSb, 2);
        pDb += __shfl_xor_sync(0xffffffffu, pDb, 1);
        pDb += __shfl_xor_sync(0xffffffffu, pDb, 2);
        if ((lane & 3) == 0) {
            atomicAdd(&sPS[rowA][hb], pSa);
            atomicAdd(&sPD[rowA][hb], pDa);
            atomicAdd(&sPS[rowB][hb], pSb);
            atomicAdd(&sPD[rowB][hb], pDb);
        }
    }
    __syncthreads();
    {
        int rr = tid >> 1, hh = tid & 1;
        int node = r0 + rr;
        int head = blockIdx.y * 2 + hh;
        float v = sPS[rr][hh];
        aS[node * 4 + head] = v;
        aD[node * 4 + head] = sPD[rr][hh];
        atomicMaxF(&sMax[hh], v);
    }
    __syncthreads();
    if (tid < 2) atomicMaxF(&maxS[blockIdx.y * 2 + tid], sMax[tid]);
}

// ---------------- segment softmax + weighted aggregate (device body) ----------
// Global-bound softmax: B = lrelu(maxS_global + aD) >= every edge logit of
// this node (lrelu monotonic) -> no per-node max pass, single edge pass.
__device__ __forceinline__ float lrelu(float v) { return v > 0.0f ? v : 0.2f * v; }

__device__ __forceinline__ void aggregate_node(
    int node, int lane, const int* __restrict__ rowptr, const int* __restrict__ csrc,
    const float* __restrict__ H, const float* __restrict__ aS,
    const float* __restrict__ aD, const float* __restrict__ bias,
    const float* __restrict__ maxS, float* __restrict__ ex, float r[8]) {
    int rs = rowptr[node], re = rowptr[node + 1];
    float4 ad = *(const float4*)(aD + node * 4);
    float4 mx = *(const float4*)maxS;
    float b0v = lrelu(mx.x + ad.x);
    float b1v = lrelu(mx.y + ad.y);
    float b2v = lrelu(mx.z + ad.z);
    float b3v = lrelu(mx.w + ad.w);

    // single pass: gather aS, exp(e - bound), store, sum
    float s0 = 0, s1 = 0, s2 = 0, s3 = 0;
    for (int e = rs + lane; e < re; e += 32) {
        int s = csrc[e];
        float4 as = *(const float4*)(aS + s * 4);
        float x0 = expf(lrelu(as.x + ad.x) - b0v);
        float x1 = expf(lrelu(as.y + ad.y) - b1v);
        float x2 = expf(lrelu(as.z + ad.z) - b2v);
        float x3 = expf(lrelu(as.w + ad.w) - b3v);
        *(float4*)(ex + e * 4) = make_float4(x0, x1, x2, x3);
        s0 += x0; s1 += x1; s2 += x2; s3 += x3;
    }
    #pragma unroll
    for (int o = 16; o > 0; o >>= 1) {
        s0 += __shfl_xor_sync(0xffffffffu, s0, o);
        s1 += __shfl_xor_sync(0xffffffffu, s1, o);
        s2 += __shfl_xor_sync(0xffffffffu, s2, o);
        s3 += __shfl_xor_sync(0xffffffffu, s3, o);
    }
    int head = lane >> 3;
    float sh = head == 0 ? s0 : head == 1 ? s1 : head == 2 ? s2 : s3;
    float inv = 1.0f / (sh + 1e-16f);

    // pass 2: scalar weighted gather (index prefetch)
    float acc[8] = {};
    int cb = lane * 8;
    int sNext = csrc[rs];
    for (int e = rs; e < re; e++) {
        int s = sNext;
        if (e + 1 < re) sNext = csrc[e + 1];
        float alpha = __ldg(ex + e * 4 + head) * inv;
        const float4* hp = (const float4*)(H + s * DMODEL + cb);
        float4 h0 = hp[0], h1 = hp[1];
        acc[0] += alpha * h0.x; acc[1] += alpha * h0.y;
        acc[2] += alpha * h0.z; acc[3] += alpha * h0.w;
        acc[4] += alpha * h1.x; acc[5] += alpha * h1.y;
        acc[6] += alpha * h1.z; acc[7] += alpha * h1.w;
    }
    const float4* bp = (const float4*)(bias + cb);
    float4 b0 = bp[0], b1 = bp[1];
    r[0] = acc[0] + b0.x; r[1] = acc[1] + b0.y; r[2] = acc[2] + b0.z; r[3] = acc[3] + b0.w;
    r[4] = acc[4] + b1.x; r[5] = acc[5] + b1.y; r[6] = acc[6] + b1.z; r[7] = acc[7] + b1.w;
    #pragma unroll
    for (int i = 0; i < 8; i++) r[i] = r[i] > 0.0f ? r[i] : 0.0f;
}

__global__ void k_aggregate(const int* __restrict__ rowptr, const int* __restrict__ csrc,
                            const float* __restrict__ H, const float* __restrict__ aS,
                            const float* __restrict__ aD, const float* __restrict__ bias,
                            const float* __restrict__ maxS,
                            float* __restrict__ ex, float* __restrict__ out) {
    int node = (blockIdx.x * blockDim.x + threadIdx.x) >> 5;
    int lane = threadIdx.x & 31;
    if (node >= NNODE) return;
    float r[8];
    aggregate_node(node, lane, rowptr, csrc, H, aS, aD, bias, maxS, ex, r);
    float* op = out + node * DMODEL + lane * 8;
    *(float4*)op       = make_float4(r[0], r[1], r[2], r[3]);
    *(float4*)(op + 4) = make_float4(r[4], r[5], r[6], r[7]);
}

// ---------------- fused: layer-3 aggregate + dec_geo + fc_geo ------------------
__global__ void __launch_bounds__(256)
k_agg_final(const int* __restrict__ rowptr, const int* __restrict__ csrc,
            const float* __restrict__ H, const float* __restrict__ aS,
            const float* __restrict__ aD, const float* __restrict__ bias,
            const float* __restrict__ maxS, float* __restrict__ ex,
            const float* __restrict__ Wg, const float* __restrict__ bg,
            const float* __restrict__ Wf, const float* __restrict__ bf,
            float* __restrict__ out) {
    __shared__ float sWg[128][FEAT];
    __shared__ float sx[8][DMODEL];
    __shared__ float sWf[FEAT * 5];

    int tid = threadIdx.x;
    int w = tid >> 5;
    int lane = tid & 31;
    int node = blockIdx.x * 8 + w;

    for (int i = tid; i < FEAT * 5; i += 256) sWf[i] = Wf[i];

    float r[8];
    aggregate_node(node, lane, rowptr, csrc, H, aS, aD, bias, maxS, ex, r);
    float* sxp = &sx[w][lane * 8];
    *(float4*)sxp       = make_float4(r[0], r[1], r[2], r[3]);
    *(float4*)(sxp + 4) = make_float4(r[4], r[5], r[6], r[7]);
    __syncthreads();

    float y0 = bg[lane], y1 = bg[lane + 32];
    #pragma unroll 1
    for (int kc = 0; kc < DMODEL; kc += 128) {
        #pragma unroll
        for (int t2 = 0; t2 < 8; t2++) {
            int idx = (tid + t2 * 256) * 4;
            *(float4*)&sWg[idx >> 6][idx & 63] =
                *(const float4*)(Wg + kc * FEAT + idx);
        }
        __syncthreads();
        #pragma unroll 4
        for (int k = 0; k < 128; k++) {
            float xv = sx[w][kc + k];
            y0 += xv * sWg[k][lane];
            y1 += xv * sWg[k][lane + 32];
        }
        __syncthreads();
    }
    y0 = y0 > 0.0f ? y0 : 0.0f;
    y1 = y1 > 0.0f ? y1 : 0.0f;

    float p[5];
    #pragma unroll
    for (int c = 0; c < 5; c++)
        p[c] = y0 * sWf[lane * 5 + c] + y1 * sWf[(lane + 32) * 5 + c];
    #pragma unroll
    for (int o = 16; o > 0; o >>= 1) {
        #pragma unroll
        for (int c = 0; c < 5; c++)
            p[c] += __shfl_xor_sync(0xffffffffu, p[c], o);
    }
    if (lane == 0) {
        #pragma unroll
        for (int c = 0; c < 5; c++)
            out[node * 5 + c] = p[c] + bf[c];
    }
}

// ---------------- host orchestration ------------------------------------------
extern "C" void kernel_launch(void* const* d_in, const int* in_sizes, int n_in,
                              void* d_out, int out_size) {
    const float* z     = (const float*)d_in[0];
    const int*   ei    = (const int*)d_in[1];
    const int*   batch = (const int*)d_in[2];
    int base = (in_sizes[3] == 1) ? 4 : 3;
    const float* W0  = (const float*)d_in[base + 0];
    const float* b0  = (const float*)d_in[base + 1];
    const float* W1  = (const float*)d_in[base + 2];
    const float* as1 = (const float*)d_in[base + 3];
    const float* ad1 = (const float*)d_in[base + 4];
    const float* bb1 = (const float*)d_in[base + 5];
    const float* W2  = (const float*)d_in[base + 6];
    const float* as2 = (const float*)d_in[base + 7];
    const float* ad2 = (const float*)d_in[base + 8];
    const float* bb2 = (const float*)d_in[base + 9];
    const float* W3  = (const float*)d_in[base + 10];
    const float* as3 = (const float*)d_in[base + 11];
    const float* ad3 = (const float*)d_in[base + 12];
    const float* bb3 = (const float*)d_in[base + 13];
    const float* Wg  = (const float*)d_in[base + 14];
    const float* bg  = (const float*)d_in[base + 15];
    const float* Wf  = (const float*)d_in[base + 16];
    const float* bf  = (const float*)d_in[base + 17];

    const int* srcArr = ei;
    const int* dstArr = ei + NEDGE;

    float *bufA, *bufB, *aS, *aD, *exB, *pgB, *maxB;
    int *startsB, *degB, *rowptrB, *cursorB, *csrcB;
    cudaGetSymbolAddress((void**)&bufA, g_bufA);
    cudaGetSymbolAddress((void**)&bufB, g_bufB);
    cudaGetSymbolAddress((void**)&aS, g_as);
    cudaGetSymbolAddress((void**)&aD, g_ad);
    cudaGetSymbolAddress((void**)&exB, g_ex);
    cudaGetSymbolAddress((void**)&pgB, g_pg);
    cudaGetSymbolAddress((void**)&maxB, g_maxS);
    cudaGetSymbolAddress((void**)&startsB, g_starts);
    cudaGetSymbolAddress((void**)&degB, g_deg);
    cudaGetSymbolAddress((void**)&rowptrB, g_rowptr);
    cudaGetSymbolAddress((void**)&cursorB, g_cursor);
    cudaGetSymbolAddress((void**)&csrcB, g_csrc);

    dim3 gemmGrid(NNODE / 128, 2);

    k_pro<<<NGRAPH + NBLK + EBLK, 256>>>(z, W0, b0, W1, pgB, batch, startsB,
                                         degB, dstArr);
    k_fill2<<<NBLK, 256>>>(degB, rowptrB, cursorB, csrcB, maxB);
    k_mid<<<WBLK + EBLK + NBLK, 256>>>(pgB, W1, batch, startsB, as1, ad1, bufB,
                                       aS, aD, srcArr, dstArr, cursorB, csrcB,
                                       degB, maxB + 0);
    k_aggregate<<<WBLK, 256>>>(rowptrB, csrcB, bufB, aS, aD, bb1, maxB + 0,
                               exB, bufA);
    k_gemm_attn<<<gemmGrid, 256>>>(bufA, W2, as2, ad2, bufB, aS, aD, maxB + 4);
    k_aggregate<<<WBLK, 256>>>(rowptrB, csrcB, bufB, aS, aD, bb2, maxB + 4,
                               exB, bufA);
    k_gemm_attn<<<gemmGrid, 256>>>(bufA, W3, as3, ad3, bufB, aS, aD, maxB + 8);
    k_agg_final<<<WBLK, 256>>>(rowptrB, csrcB, bufB, aS, aD, bb3, maxB + 8, exB,
                               Wg, bg, Wf, bf, (float*)d_out);
}

// round 12
// speedup vs baseline: 1.0950x; 1.0061x over previous
#include <cuda_runtime.h>
#include <math.h>
#include <stdint.h>

// ---------------- problem constants -----------------------------------------
#define NNODE 19200
#define NEDGE 230400
#define NGRAPH 128
#define LATENT 256
#define FEAT 64
#define HEADS 4
#define POS 180
#define DMODEL 256       // HEADS * FEAT
#define ETOT (NEDGE + NNODE)
#define NBLK 75          // NNODE / 256
#define EBLK 900         // NEDGE / 256
#define WBLK 2400        // NNODE / 8 (8 warps per block)

// ---------------- static device scratch --------------------------------------
__device__ __align__(16) float g_bufA[NNODE * DMODEL];
__device__ __align__(16) float g_bufB[NNODE * DMODEL];
__device__ __align__(16) float g_as[NNODE * HEADS];
__device__ __align__(16) float g_ad[NNODE * HEADS];
__device__ __align__(16) float g_ex[ETOT * HEADS];
__device__ __align__(16) float g_pg[NGRAPH * DMODEL];
__device__ __align__(16) float g_maxS[3][4];   // per-layer global aS max (slots)
__device__ int g_starts[NGRAPH];
__device__ int g_deg[NNODE];      // zero at load; re-zeroed each replay in k_mid
__device__ int g_rowptr[NNODE + 1];
__device__ int g_cursor[NNODE];
__device__ int g_csrc[ETOT];

__device__ __forceinline__ void atomicMaxF(float* a, float v) {
    if (v >= 0.0f) atomicMax((int*)a, __float_as_int(v));
    else           atomicMin((unsigned int*)a, __float_as_uint(v));
}

// ---------------- fused prologue: x0pg | starts | hist -------------------------
__global__ void k_pro(const float* __restrict__ z, const float* __restrict__ W0,
                      const float* __restrict__ b0, const float* __restrict__ W1,
                      float* __restrict__ pg, const int* __restrict__ batch,
                      int* __restrict__ starts, int* __restrict__ deg,
                      const int* __restrict__ dst) {
    int b = blockIdx.x;
    int t = threadIdx.x;
    if (b < NGRAPH) {
        __shared__ float xs[FEAT];
        if (t < FEAT) {
            float acc = b0[t];
            const float* zr = z + b * LATENT;
            #pragma unroll 4
            for (int k = 0; k < LATENT; k++) acc += zr[k] * W0[k * FEAT + t];
            xs[t] = acc > 0.0f ? acc : 0.0f;
        }
        __syncthreads();
        float a = 0.0f;
        #pragma unroll
        for (int k = 0; k < FEAT; k++) a += xs[k] * W1[k * DMODEL + t];
        pg[b * DMODEL + t] = a;
    } else if (b < NGRAPH + NBLK) {
        int i = (b - NGRAPH) * 256 + t;
        int bb = batch[i];
        if (i == 0 || batch[i - 1] != bb) starts[bb] = i;
    } else {
        int e = (b - NGRAPH - NBLK) * 256 + t;
        atomicAdd(&deg[dst[e]], 1);
    }
}

// ---------------- CSR: prefix + local scan + self-loop fill + maxS init --------
__global__ void k_fill2(const int* __restrict__ deg, int* __restrict__ rowptr,
                        int* __restrict__ cursor, int* __restrict__ csrc,
                        float* __restrict__ maxS) {
    __shared__ int red[256];
    __shared__ int s[256];
    int t = threadIdx.x;
    int b = blockIdx.x;
    if (b == 0 && t < 12) maxS[t] = __int_as_float(0xff800000);  // -inf, 3 slots
    int lim = b * 256;
    int sum = 0;
    for (int i = t; i < lim; i += 256) sum += deg[i] + 1;   // +1 self loop
    red[t] = sum;
    __syncthreads();
    for (int off = 128; off > 0; off >>= 1) {
        if (t < off) red[t] += red[t + off];
        __syncthreads();
    }
    int node = lim + t;
    int d = deg[node] + 1;
    s[t] = d;
    __syncthreads();
    for (int off = 1; off < 256; off <<= 1) {
        int u = (t >= off) ? s[t - off] : 0;
        __syncthreads();
        s[t] += u;
        __syncthreads();
    }
    int r = red[0] + s[t] - d;
    rowptr[node] = r;
    csrc[r] = node;                           // self loop first
    cursor[node] = r + 1;
    if (node == NNODE - 1) rowptr[NNODE] = red[0] + s[t];
}

// ---------------- fused: h1+attn | CSR scatter | deg re-zero --------------------
__global__ void k_mid(const float* __restrict__ pg, const float* __restrict__ W1,
                      const int* __restrict__ batch, const int* __restrict__ starts,
                      const float* __restrict__ attS, const float* __restrict__ attD,
                      float* __restrict__ H, float* __restrict__ aS,
                      float* __restrict__ aD,
                      const int* __restrict__ src, const int* __restrict__ dst,
                      int* __restrict__ cursor, int* __restrict__ csrc,
                      int* __restrict__ deg, float* __restrict__ maxS) {
    int b = blockIdx.x;
    int tid = threadIdx.x;
    if (b >= WBLK + EBLK) {
        deg[(b - WBLK - EBLK) * 256 + tid] = 0;
        return;
    }
    if (b >= WBLK) {
        int e = (b - WBLK) * 256 + tid;
        int p = atomicAdd(&cursor[dst[e]], 1);
        csrc[p] = src[e];
        return;
    }
    __shared__ float sS[DMODEL], sD[DMODEL];
    __shared__ float sMax[4];
    if (tid < DMODEL) { sS[tid] = attS[tid]; sD[tid] = attD[tid]; }
    if (tid < 4) sMax[tid] = __int_as_float(0xff800000);
    __syncthreads();
    int node = b * 8 + (tid >> 5);
    int lane = tid & 31;
    int g = batch[node];
    int order = node - starts[g];
    int c0 = lane * 8;
    const float4* pgr = (const float4*)(pg + g * DMODEL + c0);
    const float4* w1r = (const float4*)(W1 + (FEAT + order) * DMODEL + c0);
    float4 p0 = pgr[0], p1 = pgr[1];
    float4 w0 = w1r[0], w1v = w1r[1];
    float h[8];
    h[0] = p0.x + w0.x; h[1] = p0.y + w0.y; h[2] = p0.z + w0.z; h[3] = p0.w + w0.w;
    h[4] = p1.x + w1v.x; h[5] = p1.y + w1v.y; h[6] = p1.z + w1v.z; h[7] = p1.w + w1v.w;
    float* hr = H + node * DMODEL + c0;
    *(float4*)hr       = make_float4(h[0], h[1], h[2], h[3]);
    *(float4*)(hr + 4) = make_float4(h[4], h[5], h[6], h[7]);
    float pS = 0.0f, pD = 0.0f;
    #pragma unroll
    for (int j = 0; j < 8; j++) { pS += h[j] * sS[c0 + j]; pD += h[j] * sD[c0 + j]; }
    pS += __shfl_xor_sync(0xffffffffu, pS, 1);
    pS += __shfl_xor_sync(0xffffffffu, pS, 2);
    pS += __shfl_xor_sync(0xffffffffu, pS, 4);
    pD += __shfl_xor_sync(0xffffffffu, pD, 1);
    pD += __shfl_xor_sync(0xffffffffu, pD, 2);
    pD += __shfl_xor_sync(0xffffffffu, pD, 4);
    if ((lane & 7) == 0) {
        int hd = lane >> 3;
        aS[node * 4 + hd] = pS;
        aD[node * 4 + hd] = pD;
        atomicMaxF(&sMax[hd], pS);
    }
    __syncthreads();
    if (tid < 4) atomicMaxF(&maxS[tid], sMax[tid]);
}

// ---------------- tf32 tensor-core GEMM + fused attention logits ---------------
#define SMS 136
__device__ __forceinline__ uint32_t f2tf32(float v) {
    uint32_t r;
    asm("cvt.rna.tf32.f32 %0, %1;" : "=r"(r) : "f"(v));
    return r;
}
__device__ __forceinline__ void mma_tf32(float* c, uint32_t a0, uint32_t a1,
                                         uint32_t a2, uint32_t a3,
                                         uint32_t b0, uint32_t b1) {
    asm volatile(
        "mma.sync.aligned.m16n8k8.row.col.f32.tf32.tf32.f32 "
        "{%0,%1,%2,%3}, {%4,%5,%6,%7}, {%8,%9}, {%0,%1,%2,%3};"
        : "+f"(c[0]), "+f"(c[1]), "+f"(c[2]), "+f"(c[3])
        : "r"(a0), "r"(a1), "r"(a2), "r"(a3), "r"(b0), "r"(b1));
}

__global__ void __launch_bounds__(256, 2)
k_gemm_attn(const float* __restrict__ X, const float* __restrict__ W,
            const float* __restrict__ attS, const float* __restrict__ attD,
            float* __restrict__ C, float* __restrict__ aS, float* __restrict__ aD,
            float* __restrict__ maxS) {
    __shared__ uint32_t As[32][SMS];
    __shared__ uint32_t Bs[32][SMS];
    __shared__ float sS[128], sD[128];
    __shared__ float sPS[128][2], sPD[128][2];
    __shared__ float sMax[2];

    int tid = threadIdx.x;
    int lane = tid & 31;
    int w = tid >> 5;
    int wm = w & 1, wn = w >> 1;
    int r0 = blockIdx.x * 128;
    int c0 = blockIdx.y * 128;

    if (tid < 128) { sS[tid] = attS[c0 + tid]; sD[tid] = attD[c0 + tid]; }
    if (tid < 2) sMax[tid] = __int_as_float(0xff800000);
    {
        int rr = tid >> 1, hh = tid & 1;
        sPS[rr][hh] = 0.0f;
        sPD[rr][hh] = 0.0f;
    }

    float acc[4][4][4];
    #pragma unroll
    for (int i = 0; i < 4; i++)
        #pragma unroll
        for (int j = 0; j < 4; j++)
            #pragma unroll
            for (int q = 0; q < 4; q++) acc[i][j][q] = 0.0f;

    int am = tid >> 1;
    int ak = (tid & 1) * 16;
    int bkr = tid >> 3;
    int bn = (tid & 7) * 16;

    #pragma unroll 1
    for (int kc = 0; kc < DMODEL; kc += 32) {
        const float4* ap = (const float4*)(X + (r0 + am) * DMODEL + kc + ak);
        #pragma unroll
        for (int q = 0; q < 4; q++) {
            float4 v = ap[q];
            As[ak + q * 4 + 0][am] = f2tf32(v.x);
            As[ak + q * 4 + 1][am] = f2tf32(v.y);
            As[ak + q * 4 + 2][am] = f2tf32(v.z);
            As[ak + q * 4 + 3][am] = f2tf32(v.w);
        }
        const float4* bp = (const float4*)(W + (kc + bkr) * DMODEL + c0 + bn);
        #pragma unroll
        for (int q = 0; q < 4; q++) {
            float4 v = bp[q];
            uint4 u;
            u.x = f2tf32(v.x); u.y = f2tf32(v.y);
            u.z = f2tf32(v.z); u.w = f2tf32(v.w);
            *(uint4*)&Bs[bkr][bn + q * 4] = u;
        }
        __syncthreads();

        #pragma unroll
        for (int kk = 0; kk < 4; kk++) {
            int kb = kk * 8;
            int klo = kb + (lane & 3), khi = klo + 4;
            uint32_t afr[4][4], bfr[4][2];
            #pragma unroll
            for (int mt = 0; mt < 4; mt++) {
                int m = wm * 64 + mt * 16 + (lane >> 2);
                afr[mt][0] = As[klo][m];
                afr[mt][1] = As[klo][m + 8];
                afr[mt][2] = As[khi][m];
                afr[mt][3] = As[khi][m + 8];
            }
            #pragma unroll
            for (int nt = 0; nt < 4; nt++) {
                int n = wn * 32 + nt * 8 + (lane >> 2);
                bfr[nt][0] = Bs[klo][n];
                bfr[nt][1] = Bs[khi][n];
            }
            #pragma unroll
            for (int mt = 0; mt < 4; mt++)
                #pragma unroll
                for (int nt = 0; nt < 4; nt++)
                    mma_tf32(acc[mt][nt], afr[mt][0], afr[mt][1], afr[mt][2],
                             afr[mt][3], bfr[nt][0], bfr[nt][1]);
        }
        __syncthreads();
    }

    int hb = wn >> 1;
    #pragma unroll
    for (int mt = 0; mt < 4; mt++) {
        int rowA = wm * 64 + mt * 16 + (lane >> 2);
        int rowB = rowA + 8;
        float pSa = 0.0f, pDa = 0.0f, pSb = 0.0f, pDb = 0.0f;
        #pragma unroll
        for (int nt = 0; nt < 4; nt++) {
            int lc = wn * 32 + nt * 8 + 2 * (lane & 3);
            float s0 = sS[lc], s1 = sS[lc + 1];
            float d0 = sD[lc], d1 = sD[lc + 1];
            float* a = acc[mt][nt];
            pSa += a[0] * s0 + a[1] * s1;
            pDa += a[0] * d0 + a[1] * d1;
            pSb += a[2] * s0 + a[3] * s1;
            pDb += a[2] * d0 + a[3] * d1;
            float* cpA = C + (r0 + rowA) * DMODEL + c0 + lc;
            float* cpB = C + (r0 + rowB) * DMODEL + c0 + lc;
            *(float2*)cpA = make_float2(a[0], a[1]);
            *(float2*)cpB = make_float2(a[2], a[3]);
        }
        pSa += __shfl_xor_sync(0xffffffffu, pSa, 1);
        pSa += __shfl_xor_sync(0xffffffffu, pSa, 2);
        pDa += __shfl_xor_sync(0xffffffffu, pDa, 1);
        pDa += __shfl_xor_sync(0xffffffffu, pDa, 2);
        pSb += __shfl_xor_sync(0xffffffffu, pSb, 1);
        pSb += __shfl_xor_sync(0xffffffffu, pSb, 2);
        pDb += __shfl_xor_sync(0xffffffffu, pDb, 1);
        pDb += __shfl_xor_sync(0xffffffffu, pDb, 2);
        if ((lane & 3) == 0) {
            atomicAdd(&sPS[rowA][hb], pSa);
            atomicAdd(&sPD[rowA][hb], pDa);
            atomicAdd(&sPS[rowB][hb], pSb);
            atomicAdd(&sPD[rowB][hb], pDb);
        }
    }
    __syncthreads();
    {
        int rr = tid >> 1, hh = tid & 1;
        int node = r0 + rr;
        int head = blockIdx.y * 2 + hh;
        float v = sPS[rr][hh];
        aS[node * 4 + head] = v;
        aD[node * 4 + head] = sPD[rr][hh];
        atomicMaxF(&sMax[hh], v);
    }
    __syncthreads();
    if (tid < 2) atomicMaxF(&maxS[blockIdx.y * 2 + tid], sMax[tid]);
}

// ---------------- segment softmax + weighted aggregate (device body) ----------
// Global-bound softmax (single edge pass); inv hoisted out of the gather loop:
// out = inv * sum(ex_i * h_i) + bias.
__device__ __forceinline__ float lrelu(float v) { return v > 0.0f ? v : 0.2f * v; }

__device__ __forceinline__ void aggregate_node(
    int node, int lane, const int* __restrict__ rowptr, const int* __restrict__ csrc,
    const float* __restrict__ H, const float* __restrict__ aS,
    const float* __restrict__ aD, const float* __restrict__ bias,
    const float* __restrict__ maxS, float* __restrict__ ex, float r[8]) {
    int rs = rowptr[node], re = rowptr[node + 1];
    float4 ad = *(const float4*)(aD + node * 4);
    float4 mx = *(const float4*)maxS;
    float b0v = lrelu(mx.x + ad.x);
    float b1v = lrelu(mx.y + ad.y);
    float b2v = lrelu(mx.z + ad.z);
    float b3v = lrelu(mx.w + ad.w);

    // single pass: gather aS, exp(e - bound), store, sum
    float s0 = 0, s1 = 0, s2 = 0, s3 = 0;
    for (int e = rs + lane; e < re; e += 32) {
        int s = csrc[e];
        float4 as = *(const float4*)(aS + s * 4);
        float x0 = expf(lrelu(as.x + ad.x) - b0v);
        float x1 = expf(lrelu(as.y + ad.y) - b1v);
        float x2 = expf(lrelu(as.z + ad.z) - b2v);
        float x3 = expf(lrelu(as.w + ad.w) - b3v);
        *(float4*)(ex + e * 4) = make_float4(x0, x1, x2, x3);
        s0 += x0; s1 += x1; s2 += x2; s3 += x3;
    }
    #pragma unroll
    for (int o = 16; o > 0; o >>= 1) {
        s0 += __shfl_xor_sync(0xffffffffu, s0, o);
        s1 += __shfl_xor_sync(0xffffffffu, s1, o);
        s2 += __shfl_xor_sync(0xffffffffu, s2, o);
        s3 += __shfl_xor_sync(0xffffffffu, s3, o);
    }
    int head = lane >> 3;
    float sh = head == 0 ? s0 : head == 1 ? s1 : head == 2 ? s2 : s3;
    float inv = 1.0f / (sh + 1e-16f);

    // pass 2: raw weighted gather (no per-edge normalization)
    float acc[8] = {};
    int cb = lane * 8;
    int sNext = csrc[rs];
    for (int e = rs; e < re; e++) {
        int s = sNext;
        if (e + 1 < re) sNext = csrc[e + 1];
        float xv = __ldg(ex + e * 4 + head);
        const float4* hp = (const float4*)(H + s * DMODEL + cb);
        float4 h0 = hp[0], h1 = hp[1];
        acc[0] += xv * h0.x; acc[1] += xv * h0.y;
        acc[2] += xv * h0.z; acc[3] += xv * h0.w;
        acc[4] += xv * h1.x; acc[5] += xv * h1.y;
        acc[6] += xv * h1.z; acc[7] += xv * h1.w;
    }
    const float4* bp = (const float4*)(bias + cb);
    float4 b0 = bp[0], b1 = bp[1];
    r[0] = acc[0] * inv + b0.x; r[1] = acc[1] * inv + b0.y;
    r[2] = acc[2] * inv + b0.z; r[3] = acc[3] * inv + b0.w;
    r[4] = acc[4] * inv + b1.x; r[5] = acc[5] * inv + b1.y;
    r[6] = acc[6] * inv + b1.z; r[7] = acc[7] * inv + b1.w;
    #pragma unroll
    for (int i = 0; i < 8; i++) r[i] = r[i] > 0.0f ? r[i] : 0.0f;
}

__global__ void __launch_bounds__(256, 6)
k_aggregate(const int* __restrict__ rowptr, const int* __restrict__ csrc,
            const float* __restrict__ H, const float* __restrict__ aS,
            const float* __restrict__ aD, const float* __restrict__ bias,
            const float* __restrict__ maxS,
            float* __restrict__ ex, float* __restrict__ out) {
    int node = (blockIdx.x * blockDim.x + threadIdx.x) >> 5;
    int lane = threadIdx.x & 31;
    if (node >= NNODE) return;
    float r[8];
    aggregate_node(node, lane, rowptr, csrc, H, aS, aD, bias, maxS, ex, r);
    float* op = out + node * DMODEL + lane * 8;
    *(float4*)op       = make_float4(r[0], r[1], r[2], r[3]);
    *(float4*)(op + 4) = make_float4(r[4], r[5], r[6], r[7]);
}

// ---------------- fused: layer-3 aggregate + dec_geo + fc_geo ------------------
__global__ void __launch_bounds__(256)
k_agg_final(const int* __restrict__ rowptr, const int* __restrict__ csrc,
            const float* __restrict__ H, const float* __restrict__ aS,
            const float* __restrict__ aD, const float* __restrict__ bias,
            const float* __restrict__ maxS, float* __restrict__ ex,
            const float* __restrict__ Wg, const float* __restrict__ bg,
            const float* __restrict__ Wf, const float* __restrict__ bf,
            float* __restrict__ out) {
    __shared__ float sWg[128][FEAT];
    __shared__ float sx[8][DMODEL];
    __shared__ float sWf[FEAT * 5];

    int tid = threadIdx.x;
    int w = tid >> 5;
    int lane = tid & 31;
    int node = blockIdx.x * 8 + w;

    for (int i = tid; i < FEAT * 5; i += 256) sWf[i] = Wf[i];

    float r[8];
    aggregate_node(node, lane, rowptr, csrc, H, aS, aD, bias, maxS, ex, r);
    float* sxp = &sx[w][lane * 8];
    *(float4*)sxp       = make_float4(r[0], r[1], r[2], r[3]);
    *(float4*)(sxp + 4) = make_float4(r[4], r[5], r[6], r[7]);
    __syncthreads();

    float y0 = bg[lane], y1 = bg[lane + 32];
    #pragma unroll 1
    for (int kc = 0; kc < DMODEL; kc += 128) {
        #pragma unroll
        for (int t2 = 0; t2 < 8; t2++) {
            int idx = (tid + t2 * 256) * 4;
            *(float4*)&sWg[idx >> 6][idx & 63] =
                *(const float4*)(Wg + kc * FEAT + idx);
        }
        __syncthreads();
        #pragma unroll 4
        for (int k = 0; k < 128; k++) {
            float xv = sx[w][kc + k];
            y0 += xv * sWg[k][lane];
            y1 += xv * sWg[k][lane + 32];
        }
        __syncthreads();
    }
    y0 = y0 > 0.0f ? y0 : 0.0f;
    y1 = y1 > 0.0f ? y1 : 0.0f;

    float p[5];
    #pragma unroll
    for (int c = 0; c < 5; c++)
        p[c] = y0 * sWf[lane * 5 + c] + y1 * sWf[(lane + 32) * 5 + c];
    #pragma unroll
    for (int o = 16; o > 0; o >>= 1) {
        #pragma unroll
        for (int c = 0; c < 5; c++)
            p[c] += __shfl_xor_sync(0xffffffffu, p[c], o);
    }
    if (lane == 0) {
        #pragma unroll
        for (int c = 0; c < 5; c++)
            out[node * 5 + c] = p[c] + bf[c];
    }
}

// ---------------- host orchestration ------------------------------------------
extern "C" void kernel_launch(void* const* d_in, const int* in_sizes, int n_in,
                              void* d_out, int out_size) {
    const float* z     = (const float*)d_in[0];
    const int*   ei    = (const int*)d_in[1];
    const int*   batch = (const int*)d_in[2];
    int base = (in_sizes[3] == 1) ? 4 : 3;
    const float* W0  = (const float*)d_in[base + 0];
    const float* b0  = (const float*)d_in[base + 1];
    const float* W1  = (const float*)d_in[base + 2];
    const float* as1 = (const float*)d_in[base + 3];
    const float* ad1 = (const float*)d_in[base + 4];
    const float* bb1 = (const float*)d_in[base + 5];
    const float* W2  = (const float*)d_in[base + 6];
    const float* as2 = (const float*)d_in[base + 7];
    const float* ad2 = (const float*)d_in[base + 8];
    const float* bb2 = (const float*)d_in[base + 9];
    const float* W3  = (const float*)d_in[base + 10];
    const float* as3 = (const float*)d_in[base + 11];
    const float* ad3 = (const float*)d_in[base + 12];
    const float* bb3 = (const float*)d_in[base + 13];
    const float* Wg  = (const float*)d_in[base + 14];
    const float* bg  = (const float*)d_in[base + 15];
    const float* Wf  = (const float*)d_in[base + 16];
    const float* bf  = (const float*)d_in[base + 17];

    const int* srcArr = ei;
    const int* dstArr = ei + NEDGE;

    float *bufA, *bufB, *aS, *aD, *exB, *pgB, *maxB;
    int *startsB, *degB, *rowptrB, *cursorB, *csrcB;
    cudaGetSymbolAddress((void**)&bufA, g_bufA);
    cudaGetSymbolAddress((void**)&bufB, g_bufB);
    cudaGetSymbolAddress((void**)&aS, g_as);
    cudaGetSymbolAddress((void**)&aD, g_ad);
    cudaGetSymbolAddress((void**)&exB, g_ex);
    cudaGetSymbolAddress((void**)&pgB, g_pg);
    cudaGetSymbolAddress((void**)&maxB, g_maxS);
    cudaGetSymbolAddress((void**)&startsB, g_starts);
    cudaGetSymbolAddress((void**)&degB, g_deg);
    cudaGetSymbolAddress((void**)&rowptrB, g_rowptr);
    cudaGetSymbolAddress((void**)&cursorB, g_cursor);
    cudaGetSymbolAddress((void**)&csrcB, g_csrc);

    dim3 gemmGrid(NNODE / 128, 2);

    k_pro<<<NGRAPH + NBLK + EBLK, 256>>>(z, W0, b0, W1, pgB, batch, startsB,
                                         degB, dstArr);
    k_fill2<<<NBLK, 256>>>(degB, rowptrB, cursorB, csrcB, maxB);
    k_mid<<<WBLK + EBLK + NBLK, 256>>>(pgB, W1, batch, startsB, as1, ad1, bufB,
                                       aS, aD, srcArr, dstArr, cursorB, csrcB,
                                       degB, maxB + 0);
    k_aggregate<<<WBLK, 256>>>(rowptrB, csrcB, bufB, aS, aD, bb1, maxB + 0,
                               exB, bufA);
    k_gemm_attn<<<gemmGrid, 256>>>(bufA, W2, as2, ad2, bufB, aS, aD, maxB + 4);
    k_aggregate<<<WBLK, 256>>>(rowptrB, csrcB, bufB, aS, aD, bb2, maxB + 4,
                               exB, bufA);
    k_gemm_attn<<<gemmGrid, 256>>>(bufA, W3, as3, ad3, bufB, aS, aD, maxB + 8);
    k_agg_final<<<WBLK, 256>>>(rowptrB, csrcB, bufB, aS, aD, bb3, maxB + 8, exB,
                               Wg, bg, Wf, bf, (float*)d_out);
}

// round 13
// speedup vs baseline: 1.1079x; 1.0119x over previous
#include <cuda_runtime.h>
#include <math.h>
#include <stdint.h>

// ---------------- problem constants -----------------------------------------
#define NNODE 19200
#define NEDGE 230400
#define NGRAPH 128
#define LATENT 256
#define FEAT 64
#define HEADS 4
#define POS 180
#define DMODEL 256       // HEADS * FEAT
#define ETOT (NEDGE + NNODE)
#define NBLK 75          // NNODE / 256
#define EBLK 900         // NEDGE / 256
#define WBLK 2400        // NNODE / 8 (8 warps per block)

// ---------------- static device scratch --------------------------------------
__device__ __align__(16) float g_bufA[NNODE * DMODEL];
__device__ __align__(16) float g_bufB[NNODE * DMODEL];
__device__ __align__(16) float g_as[NNODE * HEADS];
__device__ __align__(16) float g_ad[NNODE * HEADS];
__device__ __align__(16) float g_ex[ETOT * HEADS];
__device__ __align__(16) float g_pg[NGRAPH * DMODEL];
__device__ __align__(16) float g_maxS[3][4];   // per-layer global aS max (slots)
__device__ int g_starts[NGRAPH];
__device__ int g_deg[NNODE];      // zero at load; re-zeroed each replay in k_mid
__device__ int g_rowptr[NNODE + 1];
__device__ int g_cursor[NNODE];
__device__ int g_csrc[ETOT];

__device__ __forceinline__ void atomicMaxF(float* a, float v) {
    if (v >= 0.0f) atomicMax((int*)a, __float_as_int(v));
    else           atomicMin((unsigned int*)a, __float_as_uint(v));
}

// ---------------- fused prologue: x0pg | starts | hist -------------------------
__global__ void k_pro(const float* __restrict__ z, const float* __restrict__ W0,
                      const float* __restrict__ b0, const float* __restrict__ W1,
                      float* __restrict__ pg, const int* __restrict__ batch,
                      int* __restrict__ starts, int* __restrict__ deg,
                      const int* __restrict__ dst) {
    cudaGridDependencySynchronize();
    int b = blockIdx.x;
    int t = threadIdx.x;
    if (b < NGRAPH) {
        __shared__ float xs[FEAT];
        if (t < FEAT) {
            float acc = b0[t];
            const float* zr = z + b * LATENT;
            #pragma unroll 4
            for (int k = 0; k < LATENT; k++) acc += zr[k] * W0[k * FEAT + t];
            xs[t] = acc > 0.0f ? acc : 0.0f;
        }
        __syncthreads();
        float a = 0.0f;
        #pragma unroll
        for (int k = 0; k < FEAT; k++) a += xs[k] * W1[k * DMODEL + t];
        pg[b * DMODEL + t] = a;
    } else if (b < NGRAPH + NBLK) {
        int i = (b - NGRAPH) * 256 + t;
        int bb = batch[i];
        if (i == 0 || batch[i - 1] != bb) starts[bb] = i;
    } else {
        int e = (b - NGRAPH - NBLK) * 256 + t;
        atomicAdd(&deg[dst[e]], 1);
    }
}

// ---------------- CSR: prefix + local scan + self-loop fill + maxS init --------
__global__ void k_fill2(const int* __restrict__ deg, int* __restrict__ rowptr,
                        int* __restrict__ cursor, int* __restrict__ csrc,
                        float* __restrict__ maxS) {
    cudaGridDependencySynchronize();
    __shared__ int red[256];
    __shared__ int s[256];
    int t = threadIdx.x;
    int b = blockIdx.x;
    if (b == 0 && t < 12) maxS[t] = __int_as_float(0xff800000);  // -inf, 3 slots
    int lim = b * 256;
    int sum = 0;
    for (int i = t; i < lim; i += 256) sum += deg[i] + 1;   // +1 self loop
    red[t] = sum;
    __syncthreads();
    for (int off = 128; off > 0; off >>= 1) {
        if (t < off) red[t] += red[t + off];
        __syncthreads();
    }
    int node = lim + t;
    int d = deg[node] + 1;
    s[t] = d;
    __syncthreads();
    for (int off = 1; off < 256; off <<= 1) {
        int u = (t >= off) ? s[t - off] : 0;
        __syncthreads();
        s[t] += u;
        __syncthreads();
    }
    int r = red[0] + s[t] - d;
    rowptr[node] = r;
    csrc[r] = node;                           // self loop first
    cursor[node] = r + 1;
    if (node == NNODE - 1) rowptr[NNODE] = red[0] + s[t];
}

// ---------------- fused: h1+attn | CSR scatter | deg re-zero --------------------
__global__ void k_mid(const float* __restrict__ pg, const float* __restrict__ W1,
                      const int* __restrict__ batch, const int* __restrict__ starts,
                      const float* __restrict__ attS, const float* __restrict__ attD,
                      float* __restrict__ H, float* __restrict__ aS,
                      float* __restrict__ aD,
                      const int* __restrict__ src, const int* __restrict__ dst,
                      int* __restrict__ cursor, int* __restrict__ csrc,
                      int* __restrict__ deg, float* __restrict__ maxS) {
    cudaGridDependencySynchronize();
    int b = blockIdx.x;
    int tid = threadIdx.x;
    if (b >= WBLK + EBLK) {
        deg[(b - WBLK - EBLK) * 256 + tid] = 0;
        return;
    }
    if (b >= WBLK) {
        int e = (b - WBLK) * 256 + tid;
        int p = atomicAdd(&cursor[dst[e]], 1);
        csrc[p] = src[e];
        return;
    }
    __shared__ float sS[DMODEL], sD[DMODEL];
    __shared__ float sMax[4];
    if (tid < DMODEL) { sS[tid] = attS[tid]; sD[tid] = attD[tid]; }
    if (tid < 4) sMax[tid] = __int_as_float(0xff800000);
    __syncthreads();
    int node = b * 8 + (tid >> 5);
    int lane = tid & 31;
    int g = batch[node];
    int order = node - starts[g];
    int c0 = lane * 8;
    const float4* pgr = (const float4*)(pg + g * DMODEL + c0);
    const float4* w1r = (const float4*)(W1 + (FEAT + order) * DMODEL + c0);
    float4 p0 = pgr[0], p1 = pgr[1];
    float4 w0 = w1r[0], w1v = w1r[1];
    float h[8];
    h[0] = p0.x + w0.x; h[1] = p0.y + w0.y; h[2] = p0.z + w0.z; h[3] = p0.w + w0.w;
    h[4] = p1.x + w1v.x; h[5] = p1.y + w1v.y; h[6] = p1.z + w1v.z; h[7] = p1.w + w1v.w;
    float* hr = H + node * DMODEL + c0;
    *(float4*)hr       = make_float4(h[0], h[1], h[2], h[3]);
    *(float4*)(hr + 4) = make_float4(h[4], h[5], h[6], h[7]);
    float pS = 0.0f, pD = 0.0f;
    #pragma unroll
    for (int j = 0; j < 8; j++) { pS += h[j] * sS[c0 + j]; pD += h[j] * sD[c0 + j]; }
    pS += __shfl_xor_sync(0xffffffffu, pS, 1);
    pS += __shfl_xor_sync(0xffffffffu, pS, 2);
    pS += __shfl_xor_sync(0xffffffffu, pS, 4);
    pD += __shfl_xor_sync(0xffffffffu, pD, 1);
    pD += __shfl_xor_sync(0xffffffffu, pD, 2);
    pD += __shfl_xor_sync(0xffffffffu, pD, 4);
    if ((lane & 7) == 0) {
        int hd = lane >> 3;
        aS[node * 4 + hd] = pS;
        aD[node * 4 + hd] = pD;
        atomicMaxF(&sMax[hd], pS);
    }
    __syncthreads();
    if (tid < 4) atomicMaxF(&maxS[tid], sMax[tid]);
}

// ---------------- tf32 tensor-core GEMM + fused attention logits ---------------
#define SMS 136
__device__ __forceinline__ uint32_t f2tf32(float v) {
    uint32_t r;
    asm("cvt.rna.tf32.f32 %0, %1;" : "=r"(r) : "f"(v));
    return r;
}
__device__ __forceinline__ void mma_tf32(float* c, uint32_t a0, uint32_t a1,
                                         uint32_t a2, uint32_t a3,
                                         uint32_t b0, uint32_t b1) {
    asm volatile(
        "mma.sync.aligned.m16n8k8.row.col.f32.tf32.tf32.f32 "
        "{%0,%1,%2,%3}, {%4,%5,%6,%7}, {%8,%9}, {%0,%1,%2,%3};"
        : "+f"(c[0]), "+f"(c[1]), "+f"(c[2]), "+f"(c[3])
        : "r"(a0), "r"(a1), "r"(a2), "r"(a3), "r"(b0), "r"(b1));
}

__global__ void __launch_bounds__(256, 2)
k_gemm_attn(const float* __restrict__ X, const float* __restrict__ W,
            const float* __restrict__ attS, const float* __restrict__ attD,
            float* __restrict__ C, float* __restrict__ aS, float* __restrict__ aD,
            float* __restrict__ maxS) {
    cudaGridDependencySynchronize();
    __shared__ uint32_t As[32][SMS];
    __shared__ uint32_t Bs[32][SMS];
    __shared__ float sS[128], sD[128];
    __shared__ float sPS[128][2], sPD[128][2];
    __shared__ float sMax[2];

    int tid = threadIdx.x;
    int lane = tid & 31;
    int w = tid >> 5;
    int wm = w & 1, wn = w >> 1;
    int r0 = blockIdx.x * 128;
    int c0 = blockIdx.y * 128;

    if (tid < 128) { sS[tid] = attS[c0 + tid]; sD[tid] = attD[c0 + tid]; }
    if (tid < 2) sMax[tid] = __int_as_float(0xff800000);
    {
        int rr = tid >> 1, hh = tid & 1;
        sPS[rr][hh] = 0.0f;
        sPD[rr][hh] = 0.0f;
    }

    float acc[4][4][4];
    #pragma unroll
    for (int i = 0; i < 4; i++)
        #pragma unroll
        for (int j = 0; j < 4; j++)
            #pragma unroll
            for (int q = 0; q < 4; q++) acc[i][j][q] = 0.0f;

    int am = tid >> 1;
    int ak = (tid & 1) * 16;
    int bkr = tid >> 3;
    int bn = (tid & 7) * 16;

    #pragma unroll 1
    for (int kc = 0; kc < DMODEL; kc += 32) {
        const float4* ap = (const float4*)(X + (r0 + am) * DMODEL + kc + ak);
        #pragma unroll
        for (int q = 0; q < 4; q++) {
            float4 v = ap[q];
            As[ak + q * 4 + 0][am] = f2tf32(v.x);
            As[ak + q * 4 + 1][am] = f2tf32(v.y);
            As[ak + q * 4 + 2][am] = f2tf32(v.z);
            As[ak + q * 4 + 3][am] = f2tf32(v.w);
        }
        const float4* bp = (const float4*)(W + (kc + bkr) * DMODEL + c0 + bn);
        #pragma unroll
        for (int q = 0; q < 4; q++) {
            float4 v = bp[q];
            uint4 u;
            u.x = f2tf32(v.x); u.y = f2tf32(v.y);
            u.z = f2tf32(v.z); u.w = f2tf32(v.w);
            *(uint4*)&Bs[bkr][bn + q * 4] = u;
        }
        __syncthreads();

        #pragma unroll
        for (int kk = 0; kk < 4; kk++) {
            int kb = kk * 8;
            int klo = kb + (lane & 3), khi = klo + 4;
            uint32_t afr[4][4], bfr[4][2];
            #pragma unroll
            for (int mt = 0; mt < 4; mt++) {
                int m = wm * 64 + mt * 16 + (lane >> 2);
                afr[mt][0] = As[klo][m];
                afr[mt][1] = As[klo][m + 8];
                afr[mt][2] = As[khi][m];
                afr[mt][3] = As[khi][m + 8];
            }
            #pragma unroll
            for (int nt = 0; nt < 4; nt++) {
                int n = wn * 32 + nt * 8 + (lane >> 2);
                bfr[nt][0] = Bs[klo][n];
                bfr[nt][1] = Bs[khi][n];
            }
            #pragma unroll
            for (int mt = 0; mt < 4; mt++)
                #pragma unroll
                for (int nt = 0; nt < 4; nt++)
                    mma_tf32(acc[mt][nt], afr[mt][0], afr[mt][1], afr[mt][2],
                             afr[mt][3], bfr[nt][0], bfr[nt][1]);
        }
        __syncthreads();
    }

    int hb = wn >> 1;
    #pragma unroll
    for (int mt = 0; mt < 4; mt++) {
        int rowA = wm * 64 + mt * 16 + (lane >> 2);
        int rowB = rowA + 8;
        float pSa = 0.0f, pDa = 0.0f, pSb = 0.0f, pDb = 0.0f;
        #pragma unroll
        for (int nt = 0; nt < 4; nt++) {
            int lc = wn * 32 + nt * 8 + 2 * (lane & 3);
            float s0 = sS[lc], s1 = sS[lc + 1];
            float d0 = sD[lc], d1 = sD[lc + 1];
            float* a = acc[mt][nt];
            pSa += a[0] * s0 + a[1] * s1;
            pDa += a[0] * d0 + a[1] * d1;
            pSb += a[2] * s0 + a[3] * s1;
            pDb += a[2] * d0 + a[3] * d1;
            float* cpA = C + (r0 + rowA) * DMODEL + c0 + lc;
            float* cpB = C + (r0 + rowB) * DMODEL + c0 + lc;
            *(float2*)cpA = make_float2(a[0], a[1]);
            *(float2*)cpB = make_float2(a[2], a[3]);
        }
        pSa += __shfl_xor_sync(0xffffffffu, pSa, 1);
        pSa += __shfl_xor_sync(0xffffffffu, pSa, 2);
        pDa += __shfl_xor_sync(0xffffffffu, pDa, 1);
        pDa += __shfl_xor_sync(0xffffffffu, pDa, 2);
        pSb += __shfl_xor_sync(0xffffffffu, pSb, 1);
        pSb += __shfl_xor_sync(0xffffffffu, pSb, 2);
        pDb += __shfl_xor_sync(0xffffffffu, pDb, 1);
        pDb += __shfl_xor_sync(0xffffffffu, pDb, 2);
        if ((lane & 3) == 0) {
            atomicAdd(&sPS[rowA][hb], pSa);
            atomicAdd(&sPD[rowA][hb], pDa);
            atomicAdd(&sPS[rowB][hb], pSb);
            atomicAdd(&sPD[rowB][hb], pDb);
        }
    }
    __syncthreads();
    {
        int rr = tid >> 1, hh = tid & 1;
        int node = r0 + rr;
        int head = blockIdx.y * 2 + hh;
        float v = sPS[rr][hh];
        aS[node * 4 + head] = v;
        aD[node * 4 + head] = sPD[rr][hh];
        atomicMaxF(&sMax[hh], v);
    }
    __syncthreads();
    if (tid < 2) atomicMaxF(&maxS[blockIdx.y * 2 + tid], sMax[tid]);
}

// ---------------- segment softmax + weighted aggregate (device body) ----------
__device__ __forceinline__ float lrelu(float v) { return v > 0.0f ? v : 0.2f * v; }

__device__ __forceinline__ void aggregate_node(
    int node, int lane, const int* __restrict__ rowptr, const int* __restrict__ csrc,
    const float* __restrict__ H, const float* __restrict__ aS,
    const float* __restrict__ aD, const float* __restrict__ bias,
    const float* __restrict__ maxS, float* __restrict__ ex, float r[8]) {
    int rs = rowptr[node], re = rowptr[node + 1];
    float4 ad = *(const float4*)(aD + node * 4);
    float4 mx = *(const float4*)maxS;
    float b0v = lrelu(mx.x + ad.x);
    float b1v = lrelu(mx.y + ad.y);
    float b2v = lrelu(mx.z + ad.z);
    float b3v = lrelu(mx.w + ad.w);

    float s0 = 0, s1 = 0, s2 = 0, s3 = 0;
    for (int e = rs + lane; e < re; e += 32) {
        int s = csrc[e];
        float4 as = *(const float4*)(aS + s * 4);
        float x0 = expf(lrelu(as.x + ad.x) - b0v);
        float x1 = expf(lrelu(as.y + ad.y) - b1v);
        float x2 = expf(lrelu(as.z + ad.z) - b2v);
        float x3 = expf(lrelu(as.w + ad.w) - b3v);
        *(float4*)(ex + e * 4) = make_float4(x0, x1, x2, x3);
        s0 += x0; s1 += x1; s2 += x2; s3 += x3;
    }
    #pragma unroll
    for (int o = 16; o > 0; o >>= 1) {
        s0 += __shfl_xor_sync(0xffffffffu, s0, o);
        s1 += __shfl_xor_sync(0xffffffffu, s1, o);
        s2 += __shfl_xor_sync(0xffffffffu, s2, o);
        s3 += __shfl_xor_sync(0xffffffffu, s3, o);
    }
    int head = lane >> 3;
    float sh = head == 0 ? s0 : head == 1 ? s1 : head == 2 ? s2 : s3;
    float inv = 1.0f / (sh + 1e-16f);

    float acc[8] = {};
    int cb = lane * 8;
    int sNext = csrc[rs];
    for (int e = rs; e < re; e++) {
        int s = sNext;
        if (e + 1 < re) sNext = csrc[e + 1];
        float xv = __ldg(ex + e * 4 + head);
        const float4* hp = (const float4*)(H + s * DMODEL + cb);
        float4 h0 = hp[0], h1 = hp[1];
        acc[0] += xv * h0.x; acc[1] += xv * h0.y;
        acc[2] += xv * h0.z; acc[3] += xv * h0.w;
        acc[4] += xv * h1.x; acc[5] += xv * h1.y;
        acc[6] += xv * h1.z; acc[7] += xv * h1.w;
    }
    const float4* bp = (const float4*)(bias + cb);
    float4 b0 = bp[0], b1 = bp[1];
    r[0] = acc[0] * inv + b0.x; r[1] = acc[1] * inv + b0.y;
    r[2] = acc[2] * inv + b0.z; r[3] = acc[3] * inv + b0.w;
    r[4] = acc[4] * inv + b1.x; r[5] = acc[5] * inv + b1.y;
    r[6] = acc[6] * inv + b1.z; r[7] = acc[7] * inv + b1.w;
    #pragma unroll
    for (int i = 0; i < 8; i++) r[i] = r[i] > 0.0f ? r[i] : 0.0f;
}

__global__ void k_aggregate(const int* __restrict__ rowptr, const int* __restrict__ csrc,
                            const float* __restrict__ H, const float* __restrict__ aS,
                            const float* __restrict__ aD, const float* __restrict__ bias,
                            const float* __restrict__ maxS,
                            float* __restrict__ ex, float* __restrict__ out) {
    cudaGridDependencySynchronize();
    int node = (blockIdx.x * blockDim.x + threadIdx.x) >> 5;
    int lane = threadIdx.x & 31;
    if (node >= NNODE) return;
    float r[8];
    aggregate_node(node, lane, rowptr, csrc, H, aS, aD, bias, maxS, ex, r);
    float* op = out + node * DMODEL + lane * 8;
    *(float4*)op       = make_float4(r[0], r[1], r[2], r[3]);
    *(float4*)(op + 4) = make_float4(r[4], r[5], r[6], r[7]);
}

// ---------------- fused: layer-3 aggregate + dec_geo + fc_geo ------------------
__global__ void __launch_bounds__(256)
k_agg_final(const int* __restrict__ rowptr, const int* __restrict__ csrc,
            const float* __restrict__ H, const float* __restrict__ aS,
            const float* __restrict__ aD, const float* __restrict__ bias,
            const float* __restrict__ maxS, float* __restrict__ ex,
            const float* __restrict__ Wg, const float* __restrict__ bg,
            const float* __restrict__ Wf, const float* __restrict__ bf,
            float* __restrict__ out) {
    cudaGridDependencySynchronize();
    __shared__ float sWg[128][FEAT];
    __shared__ float sx[8][DMODEL];
    __shared__ float sWf[FEAT * 5];

    int tid = threadIdx.x;
    int w = tid >> 5;
    int lane = tid & 31;
    int node = blockIdx.x * 8 + w;

    for (int i = tid; i < FEAT * 5; i += 256) sWf[i] = Wf[i];

    float r[8];
    aggregate_node(node, lane, rowptr, csrc, H, aS, aD, bias, maxS, ex, r);
    float* sxp = &sx[w][lane * 8];
    *(float4*)sxp       = make_float4(r[0], r[1], r[2], r[3]);
    *(float4*)(sxp + 4) = make_float4(r[4], r[5], r[6], r[7]);
    __syncthreads();

    float y0 = bg[lane], y1 = bg[lane + 32];
    #pragma unroll 1
    for (int kc = 0; kc < DMODEL; kc += 128) {
        #pragma unroll
        for (int t2 = 0; t2 < 8; t2++) {
            int idx = (tid + t2 * 256) * 4;
            *(float4*)&sWg[idx >> 6][idx & 63] =
                *(const float4*)(Wg + kc * FEAT + idx);
        }
        __syncthreads();
        #pragma unroll 4
        for (int k = 0; k < 128; k++) {
            float xv = sx[w][kc + k];
            y0 += xv * sWg[k][lane];
            y1 += xv * sWg[k][lane + 32];
        }
        __syncthreads();
    }
    y0 = y0 > 0.0f ? y0 : 0.0f;
    y1 = y1 > 0.0f ? y1 : 0.0f;

    float p[5];
    #pragma unroll
    for (int c = 0; c < 5; c++)
        p[c] = y0 * sWf[lane * 5 + c] + y1 * sWf[(lane + 32) * 5 + c];
    #pragma unroll
    for (int o = 16; o > 0; o >>= 1) {
        #pragma unroll
        for (int c = 0; c < 5; c++)
            p[c] += __shfl_xor_sync(0xffffffffu, p[c], o);
    }
    if (lane == 0) {
        #pragma unroll
        for (int c = 0; c < 5; c++)
            out[node * 5 + c] = p[c] + bf[c];
    }
}

// ---------------- host: PDL launch helper --------------------------------------
static inline void launch_pdl(const void* func, dim3 grid, dim3 block, void** args) {
    cudaLaunchConfig_t cfg = {};
    cfg.gridDim = grid;
    cfg.blockDim = block;
    cfg.dynamicSmemBytes = 0;
    cfg.stream = 0;
    cudaLaunchAttribute attr[1];
    attr[0].id = cudaLaunchAttributeProgrammaticStreamSerialization;
    attr[0].val.programmaticStreamSerializationAllowed = 1;
    cfg.attrs = attr;
    cfg.numAttrs = 1;
    cudaLaunchKernelExC(&cfg, func, args);
}

// ---------------- host orchestration ------------------------------------------
extern "C" void kernel_launch(void* const* d_in, const int* in_sizes, int n_in,
                              void* d_out, int out_size) {
    const float* z     = (const float*)d_in[0];
    const int*   ei    = (const int*)d_in[1];
    const int*   batch = (const int*)d_in[2];
    int base = (in_sizes[3] == 1) ? 4 : 3;
    const float* W0  = (const float*)d_in[base + 0];
    const float* b0  = (const float*)d_in[base + 1];
    const float* W1  = (const float*)d_in[base + 2];
    const float* as1 = (const float*)d_in[base + 3];
    const float* ad1 = (const float*)d_in[base + 4];
    const float* bb1 = (const float*)d_in[base + 5];
    const float* W2  = (const float*)d_in[base + 6];
    const float* as2 = (const float*)d_in[base + 7];
    const float* ad2 = (const float*)d_in[base + 8];
    const float* bb2 = (const float*)d_in[base + 9];
    const float* W3  = (const float*)d_in[base + 10];
    const float* as3 = (const float*)d_in[base + 11];
    const float* ad3 = (const float*)d_in[base + 12];
    const float* bb3 = (const float*)d_in[base + 13];
    const float* Wg  = (const float*)d_in[base + 14];
    const float* bg  = (const float*)d_in[base + 15];
    const float* Wf  = (const float*)d_in[base + 16];
    const float* bf  = (const float*)d_in[base + 17];

    const int* srcArr = ei;
    const int* dstArr = ei + NEDGE;

    float *bufA, *bufB, *aS, *aD, *exB, *pgB, *maxB;
    int *startsB, *degB, *rowptrB, *cursorB, *csrcB;
    cudaGetSymbolAddress((void**)&bufA, g_bufA);
    cudaGetSymbolAddress((void**)&bufB, g_bufB);
    cudaGetSymbolAddress((void**)&aS, g_as);
    cudaGetSymbolAddress((void**)&aD, g_ad);
    cudaGetSymbolAddress((void**)&exB, g_ex);
    cudaGetSymbolAddress((void**)&pgB, g_pg);
    cudaGetSymbolAddress((void**)&maxB, g_maxS);
    cudaGetSymbolAddress((void**)&startsB, g_starts);
    cudaGetSymbolAddress((void**)&degB, g_deg);
    cudaGetSymbolAddress((void**)&rowptrB, g_rowptr);
    cudaGetSymbolAddress((void**)&cursorB, g_cursor);
    cudaGetSymbolAddress((void**)&csrcB, g_csrc);

    float* max0 = maxB;
    float* max1 = maxB + 4;
    float* max2 = maxB + 8;
    float* outP = (float*)d_out;

    // 1: prologue
    {
        void* a[] = {&z, &W0, &b0, &W1, &pgB, &batch, &startsB, &degB, &dstArr};
        launch_pdl((const void*)k_pro, dim3(NGRAPH + NBLK + EBLK), dim3(256), a);
    }
    // 2: CSR rowptr + fill
    {
        void* a[] = {&degB, &rowptrB, &cursorB, &csrcB, &maxB};
        launch_pdl((const void*)k_fill2, dim3(NBLK), dim3(256), a);
    }
    // 3: h1+attn | scatter | deg re-zero
    {
        void* a[] = {&pgB, &W1, &batch, &startsB, &as1, &ad1, &bufB, &aS, &aD,
                     &srcArr, &dstArr, &cursorB, &csrcB, &degB, &max0};
        launch_pdl((const void*)k_mid, dim3(WBLK + EBLK + NBLK), dim3(256), a);
    }
    // 4: aggregate layer 1
    {
        void* a[] = {&rowptrB, &csrcB, &bufB, &aS, &aD, &bb1, &max0, &exB, &bufA};
        launch_pdl((const void*)k_aggregate, dim3(WBLK), dim3(256), a);
    }
    // 5: layer-2 GEMM
    {
        void* a[] = {&bufA, &W2, &as2, &ad2, &bufB, &aS, &aD, &max1};
        launch_pdl((const void*)k_gemm_attn, dim3(NNODE / 128, 2), dim3(256), a);
    }
    // 6: aggregate layer 2
    {
        void* a[] = {&rowptrB, &csrcB, &bufB, &aS, &aD, &bb2, &max1, &exB, &bufA};
        launch_pdl((const void*)k_aggregate, dim3(WBLK), dim3(256), a);
    }
    // 7: layer-3 GEMM
    {
        void* a[] = {&bufA, &W3, &as3, &ad3, &bufB, &aS, &aD, &max2};
        launch_pdl((const void*)k_gemm_attn, dim3(NNODE / 128, 2), dim3(256), a);
    }
    // 8: layer-3 aggregate + dec_geo + fc_geo
    {
        void* a[] = {&rowptrB, &csrcB, &bufB, &aS, &aD, &bb3, &max2, &exB,
                     &Wg, &bg, &Wf, &bf, &outP};
        launch_pdl((const void*)k_agg_final, dim3(WBLK), dim3(256), a);
    }
}